// round 13
// baseline (speedup 1.0000x reference)
#include <cuda_runtime.h>
#include <cuda_bf16.h>
#include <math.h>
#include <stdint.h>

typedef __nv_bfloat16 bf16;

// ---------------- problem constants ----------------
static const int kS   = 2048;
static const int kD   = 1024;
static const int kH   = 16;
static const int kHD  = 64;
static const int kE   = 8;
static const int kHID = 4096;

// ---------------- scratch ----------------
__device__ bf16  g_xnb     [kS*kD];
__device__ float g_qkv     [kS*3*kD];
__device__ bf16  g_qb      [kS*kD];
__device__ bf16  g_kb      [kS*kD];
__device__ bf16  g_vb      [kS*kD];
__device__ float g_Qm      [kHD*kHD];
__device__ float g_cos     [kS*32];
__device__ float g_sin     [kS*32];
__device__ bf16  g_attnb   [kS*kD];
__device__ float g_attnproj[kS*kD];
__device__ bf16  g_attnprojb[kS*kD];
__device__ float g_xmid    [kS*kD];
__device__ float g_xn2     [kS*kD];
__device__ bf16  g_xn2b    [kS*kD];
__device__ float g_rowsum  [kS];
__device__ int   g_cnt     [kE];
__device__ int   g_list    [kE*kS];
__device__ int   g_tokslot [kS*3];
__device__ float g_tokw    [kS*3];
__device__ bf16  g_gbufb   [kE*kS*kHID];
__device__ float g_ybuf    [kE*kS*kD];
// bf16 weights
__device__ bf16  g_wqkvb   [kD*3*kD];
__device__ bf16  g_woutb   [kD*kD];
__device__ bf16  g_wgateb  [kD*kD];
__device__ bf16  g_w12b    [kE*kD*2*kHID];   // column-interleaved [h1 8 | h2 8 | ...]
__device__ bf16  g_w3b     [kE*kHID*kD];

// ================= helpers =================
static __device__ __forceinline__ uint32_t s2u(const void* p) {
    uint32_t a;
    asm("{ .reg .u64 t; cvta.to.shared.u64 t, %1; cvt.u32.u64 %0, t; }" : "=r"(a) : "l"(p));
    return a;
}
#define CPA16(dst, src, sz) \
    asm volatile("cp.async.cg.shared.global [%0], [%1], 16, %2;" :: "r"(dst), "l"(src), "r"(sz))
#define CPA_COMMIT() asm volatile("cp.async.commit_group;" ::: "memory")
#define CPA_WAIT2()  asm volatile("cp.async.wait_group 2;" ::: "memory")
#define CPA_WAIT1()  asm volatile("cp.async.wait_group 1;" ::: "memory")
#define CPA_WAIT0()  asm volatile("cp.async.wait_group 0;" ::: "memory")

#define LDSM4(r0,r1,r2,r3,addr) \
    asm volatile("ldmatrix.sync.aligned.m8n8.x4.shared.b16 {%0,%1,%2,%3}, [%4];" \
        : "=r"(r0),"=r"(r1),"=r"(r2),"=r"(r3) : "r"(addr))
#define LDSM4T(r0,r1,r2,r3,addr) \
    asm volatile("ldmatrix.sync.aligned.m8n8.x4.trans.shared.b16 {%0,%1,%2,%3}, [%4];" \
        : "=r"(r0),"=r"(r1),"=r"(r2),"=r"(r3) : "r"(addr))

#define MMAB(c, a, b0v, b1v) \
    asm volatile("mma.sync.aligned.m16n8k16.row.col.f32.bf16.bf16.f32 " \
        "{%0,%1,%2,%3}, {%4,%5,%6,%7}, {%8,%9}, {%0,%1,%2,%3};" \
        : "+f"((c)[0]),"+f"((c)[1]),"+f"((c)[2]),"+f"((c)[3]) \
        : "r"((a)[0]),"r"((a)[1]),"r"((a)[2]),"r"((a)[3]), "r"(b0v),"r"(b1v))

static __device__ __forceinline__ uint32_t pack2(float a, float b) {
    __nv_bfloat162 t = __floats2bfloat162_rn(a, b);
    return *(uint32_t*)&t;
}

// ================= bf16 mma GEMM: PERSISTENT tiles, 4-stage pipeline =================
// Block tile 128x128, 8 warps of 64x32, __launch_bounds__(256,2), grid = 296 CTAs.
// Grid-strided loop over (bx, by, ez) tile space — no tail waves.
// MODE 0: C = A@B (+ optional bf16 Cb)
// MODE 1: C = X1 + X2 * sigmoid(A@B + bias)
// MODE 2: MoE pass1, fused SwiGLU: Cb = silu(h1)*h2, w12 col-interleaved
// MODE 3: MoE pass2
#define AST 40
#define BST2 136
#define NSTG 4
template <int MODE>
__global__ void __launch_bounds__(256, 2) tgemm_k(
    const bf16* __restrict__ A0, const bf16* __restrict__ B0, float* __restrict__ C0,
    bf16* __restrict__ Cb0, int M, int N, int K,
    const float* __restrict__ X1, const float* __restrict__ X2, const float* __restrict__ bias,
    int tilesX, int tilesY, int tilesZ) {
    const int NJ = 4;
    const uint32_t ASTG2 = 128 * AST * 2;
    const uint32_t BSTG2 = 32 * BST2 * 2;

    extern __shared__ bf16 sm_g[];
    bf16* As = sm_g;                       // NSTG stages [128][AST]
    bf16* Bs = sm_g + NSTG * 128 * AST;    // NSTG stages [32][BST2]

    int tid = threadIdx.x;
    // tile-independent per-thread constants
    int arow = tid >> 2, aseg = tid & 3;
    int brow = tid >> 4, bseg = tid & 15;
    uint32_t adst0 = s2u(As + arow * AST + aseg * 8);
    uint32_t adst1 = s2u(As + (arow + 64) * AST + aseg * 8);
    uint32_t bdst0 = s2u(Bs + brow * BST2 + bseg * 8);
    uint32_t bdst1 = s2u(Bs + (brow + 16) * BST2 + bseg * 8);
    int wid = tid >> 5, lane = tid & 31;
    int wm = (wid >> 2) * 64, wn = (wid & 3) * 32;
    int l15 = lane & 15, lh = (lane >> 4) * 8;
    uint32_t abase   = s2u(As) + ((wm + l15) * AST + lh) * 2;
    uint32_t bbase_s = s2u(Bs) + (l15 * BST2 + wn + lh) * 2;
    int grp = lane >> 2, qid = lane & 3;

    int total = tilesX * tilesY * tilesZ;
    int nch = K / 32;

    for (int t = blockIdx.x; t < total; t += gridDim.x) {
        int bx = t % tilesX;
        int rem = t / tilesX;
        int by = rem % tilesY;
        int ez = rem / tilesY;

        const bf16* A = A0; const bf16* B = B0;
        float* C = C0; bf16* Cb = Cb0;
        int Mt = M;
        const int* rowlist = nullptr;
        if (MODE == 2) {
            Mt = g_cnt[ez]; rowlist = g_list + ez * kS;
            B += (size_t)ez * (size_t)K * (size_t)N;
            Cb += (size_t)ez * (size_t)kS * (size_t)kHID;
        } else if (MODE == 3) {
            Mt = g_cnt[ez];
            A += (size_t)ez * (size_t)kS * (size_t)K;
            B += (size_t)ez * (size_t)K * (size_t)N;
            C += (size_t)ez * (size_t)kS * (size_t)N;
        }
        int m0 = bx * 128, n0 = by * 128;
        if (m0 >= Mt) continue;   // uniform across block

        // ---- per-tile A pointers ----
        const bf16* aptr0 = A; const bf16* aptr1 = A;
        uint32_t asz0 = 0, asz1 = 0;
        {
            int r0 = m0 + arow, r1 = r0 + 64;
            if (r0 < Mt) { int gr = (MODE == 2) ? rowlist[r0] : r0; aptr0 = A + (size_t)gr * K + aseg * 8; asz0 = 16; }
            if (r1 < Mt) { int gr = (MODE == 2) ? rowlist[r1] : r1; aptr1 = A + (size_t)gr * K + aseg * 8; asz1 = 16; }
        }
        const bf16* bbaseg = B + n0;

        auto load_chunk = [&](int c, int st) {
            CPA16(adst0 + st * ASTG2, aptr0 + c * 32, asz0);
            CPA16(adst1 + st * ASTG2, aptr1 + c * 32, asz1);
            CPA16(bdst0 + st * BSTG2, bbaseg + (size_t)(c * 32 + brow) * N + bseg * 8, 16u);
            CPA16(bdst1 + st * BSTG2, bbaseg + (size_t)(c * 32 + brow + 16) * N + bseg * 8, 16u);
        };

        float c[4][NJ][4];
#pragma unroll
        for (int i = 0; i < 4; i++)
#pragma unroll
            for (int j = 0; j < NJ; j++)
#pragma unroll
                for (int r = 0; r < 4; r++) c[i][j][r] = 0.f;

        load_chunk(0, 0); CPA_COMMIT();
        load_chunk(1, 1); CPA_COMMIT();
        load_chunk(2, 2); CPA_COMMIT();

        for (int cc = 0; cc < nch; cc++) {
            int st = cc % NSTG;
            CPA_WAIT2();
            __syncthreads();
            if (cc + 3 < nch) load_chunk(cc + 3, (cc + 3) % NSTG);
            CPA_COMMIT();
#pragma unroll
            for (int kk = 0; kk < 32; kk += 16) {
                uint32_t af[4][4];
#pragma unroll
                for (int mi = 0; mi < 4; mi++)
                    LDSM4(af[mi][0], af[mi][1], af[mi][2], af[mi][3],
                          abase + st * ASTG2 + (mi * 16 * AST + kk) * 2);
                uint32_t bq[8];
                LDSM4T(bq[0], bq[1], bq[2], bq[3], bbase_s + st * BSTG2 + (kk * BST2) * 2);
                LDSM4T(bq[4], bq[5], bq[6], bq[7], bbase_s + st * BSTG2 + (kk * BST2 + 16) * 2);
#pragma unroll
                for (int mi = 0; mi < 4; mi++)
#pragma unroll
                    for (int nj = 0; nj < NJ; nj++)
                        MMAB(c[mi][nj], af[mi], bq[nj * 2], bq[nj * 2 + 1]);
            }
        }

        __syncthreads();   // all compute done; epilogue reads regs only
#pragma unroll
        for (int mi = 0; mi < 4; mi++) {
#pragma unroll
            for (int half = 0; half < 2; half++) {
                int row = m0 + wm + mi * 16 + grp + half * 8;
                if (row >= Mt) continue;
                if (MODE == 2) {
                    size_t rb2 = (size_t)row * kHID;
#pragma unroll
                    for (int njp = 0; njp < NJ; njp += 2) {
                        int cb = n0 + wn + njp * 8 + qid * 2;
                        int oc = ((cb >> 4) << 3) + (cb & 7);
                        float h1a = c[mi][njp][half * 2], h1b = c[mi][njp][half * 2 + 1];
                        float h2a = c[mi][njp + 1][half * 2], h2b = c[mi][njp + 1][half * 2 + 1];
                        float g0 = h1a / (1.f + __expf(-h1a)) * h2a;
                        float g1 = h1b / (1.f + __expf(-h1b)) * h2b;
                        *(__nv_bfloat162*)(Cb + rb2 + oc) = __floats2bfloat162_rn(g0, g1);
                    }
                    continue;
                }
                size_t rb = (size_t)row * N;
#pragma unroll
                for (int nj = 0; nj < NJ; nj++) {
                    int col = n0 + wn + nj * 8 + qid * 2;
                    float v0 = c[mi][nj][half * 2 + 0];
                    float v1 = c[mi][nj][half * 2 + 1];
                    if (MODE == 1) {
                        float g0 = 1.f / (1.f + __expf(-(v0 + bias[col])));
                        float g1 = 1.f / (1.f + __expf(-(v1 + bias[col + 1])));
                        float o0 = X1[rb + col] + X2[rb + col] * g0;
                        float o1 = X1[rb + col + 1] + X2[rb + col + 1] * g1;
                        *(float2*)(C + rb + col) = make_float2(o0, o1);
                    } else {
                        *(float2*)(C + rb + col) = make_float2(v0, v1);
                        if (MODE == 0 && Cb)
                            *(__nv_bfloat162*)(Cb + rb + col) = __floats2bfloat162_rn(v0, v1);
                    }
                }
            }
        }
    }
}

// ================= bf16 mma flash attention: 128-q tile, 8 warps x 16 rows =================
__global__ void __launch_bounds__(256) fattn_k() {
    extern __shared__ char sm_[];
    bf16* Qs = (bf16*)sm_;              // [128][72]
    bf16* Ks = Qs + 128 * 72;           // 2 x [128][72]
    bf16* Vs = Ks + 2 * 128 * 72;       // 2 x [128][72]
    int h = blockIdx.y, q0 = blockIdx.x * 128;
    int tid = threadIdx.x, wid = tid >> 5, lane = tid & 31;
    int l15 = lane & 15, lh = (lane >> 4) * 8;
    int grp = lane >> 2, qid = lane & 3;

    {
        int r = tid >> 1, sb = (tid & 1) * 4;
        const bf16* src = g_qb + (size_t)(q0 + r) * kD + h * 64 + sb * 8;
        uint32_t dst = s2u(Qs + r * 72 + sb * 8);
#pragma unroll
        for (int j = 0; j < 4; j++) CPA16(dst + j * 16, src + j * 8, 16u);
    }
    auto loadKV = [&](int it, int buf) {
        int k0 = it * 128;
        int r = tid >> 1, sb = (tid & 1) * 4;
        const bf16* ks = g_kb + (size_t)(k0 + r) * kD + h * 64 + sb * 8;
        const bf16* vs = g_vb + (size_t)(k0 + r) * kD + h * 64 + sb * 8;
        uint32_t kd = s2u(Ks + buf * 9216 + r * 72 + sb * 8);
        uint32_t vd = s2u(Vs + buf * 9216 + r * 72 + sb * 8);
#pragma unroll
        for (int j = 0; j < 4; j++) { CPA16(kd + j * 16, ks + j * 8, 16u); CPA16(vd + j * 16, vs + j * 8, 16u); }
    };
    loadKV(0, 0); CPA_COMMIT();

    uint32_t qf[4][4];
    float m0 = -1e30f, m1 = -1e30f, l0 = 0.f, l1 = 0.f;
    float co[8][4];
#pragma unroll
    for (int j = 0; j < 8; j++)
#pragma unroll
        for (int r = 0; r < 4; r++) co[j][r] = 0.f;

    for (int it = 0; it < 16; it++) {
        int buf = it & 1;
        if (it + 1 < 16) { loadKV(it + 1, buf ^ 1); CPA_COMMIT(); CPA_WAIT1(); }
        else CPA_WAIT0();
        __syncthreads();
        if (it == 0) {
            uint32_t qb_ = s2u(Qs) + ((wid * 16 + l15) * 72 + lh) * 2;
#pragma unroll
            for (int kk4 = 0; kk4 < 4; kk4++)
                LDSM4(qf[kk4][0], qf[kk4][1], qf[kk4][2], qf[kk4][3], qb_ + kk4 * 32);
        }
        float cs[16][4];
#pragma unroll
        for (int ng = 0; ng < 16; ng++)
#pragma unroll
            for (int r = 0; r < 4; r++) cs[ng][r] = 0.f;
        uint32_t kb_ = s2u(Ks) + buf * 18432;
        int krow = (lane & 7) + ((lane >> 4) << 3);
        int kofs = ((lane >> 3) & 1) << 3;
#pragma unroll
        for (int kk4 = 0; kk4 < 4; kk4++) {
#pragma unroll
            for (int nb = 0; nb < 8; nb++) {
                uint32_t b0, b1, b2, b3;
                LDSM4(b0, b1, b2, b3, kb_ + ((nb * 16 + krow) * 72 + kk4 * 16 + kofs) * 2);
                MMAB(cs[2 * nb], qf[kk4], b0, b1);
                MMAB(cs[2 * nb + 1], qf[kk4], b2, b3);
            }
        }
        float mx0 = -1e30f, mx1 = -1e30f;
#pragma unroll
        for (int ng = 0; ng < 16; ng++) {
            mx0 = fmaxf(mx0, fmaxf(cs[ng][0], cs[ng][1]));
            mx1 = fmaxf(mx1, fmaxf(cs[ng][2], cs[ng][3]));
        }
        mx0 = fmaxf(mx0, __shfl_xor_sync(0xffffffffu, mx0, 1));
        mx0 = fmaxf(mx0, __shfl_xor_sync(0xffffffffu, mx0, 2));
        mx1 = fmaxf(mx1, __shfl_xor_sync(0xffffffffu, mx1, 1));
        mx1 = fmaxf(mx1, __shfl_xor_sync(0xffffffffu, mx1, 2));
        float nm0 = fmaxf(m0, mx0), nm1 = fmaxf(m1, mx1);
        float a0 = __expf(m0 - nm0), a1 = __expf(m1 - nm1);
        l0 *= a0; l1 *= a1;
#pragma unroll
        for (int j = 0; j < 8; j++) {
            co[j][0] *= a0; co[j][1] *= a0; co[j][2] *= a1; co[j][3] *= a1;
        }
#pragma unroll
        for (int ng = 0; ng < 16; ng++) {
            float p0 = __expf(cs[ng][0] - nm0), p1 = __expf(cs[ng][1] - nm0);
            float p2 = __expf(cs[ng][2] - nm1), p3 = __expf(cs[ng][3] - nm1);
            l0 += p0 + p1; l1 += p2 + p3;
            cs[ng][0] = p0; cs[ng][1] = p1; cs[ng][2] = p2; cs[ng][3] = p3;
        }
        m0 = nm0; m1 = nm1;
        uint32_t pf[8][4];
#pragma unroll
        for (int kg = 0; kg < 8; kg++) {
            pf[kg][0] = pack2(cs[2 * kg][0], cs[2 * kg][1]);
            pf[kg][1] = pack2(cs[2 * kg][2], cs[2 * kg][3]);
            pf[kg][2] = pack2(cs[2 * kg + 1][0], cs[2 * kg + 1][1]);
            pf[kg][3] = pack2(cs[2 * kg + 1][2], cs[2 * kg + 1][3]);
        }
        uint32_t vb_ = s2u(Vs) + buf * 18432;
#pragma unroll
        for (int kg = 0; kg < 8; kg++) {
#pragma unroll
            for (int vb = 0; vb < 4; vb++) {
                uint32_t t0, t1, t2, t3;
                LDSM4T(t0, t1, t2, t3, vb_ + ((kg * 16 + l15) * 72 + vb * 16 + lh) * 2);
                MMAB(co[2 * vb], pf[kg], t0, t1);
                MMAB(co[2 * vb + 1], pf[kg], t2, t3);
            }
        }
        __syncthreads();
    }
    l0 += __shfl_xor_sync(0xffffffffu, l0, 1);
    l0 += __shfl_xor_sync(0xffffffffu, l0, 2);
    l1 += __shfl_xor_sync(0xffffffffu, l1, 1);
    l1 += __shfl_xor_sync(0xffffffffu, l1, 2);
    float i0 = 1.f / l0, i1 = 1.f / l1;
    int r0 = q0 + wid * 16 + grp, r1 = r0 + 8;
#pragma unroll
    for (int j = 0; j < 8; j++) {
        int col = h * 64 + j * 8 + qid * 2;
        *(__nv_bfloat162*)(g_attnb + (size_t)r0 * kD + col) = __floats2bfloat162_rn(co[j][0] * i0, co[j][1] * i0);
        *(__nv_bfloat162*)(g_attnb + (size_t)r1 * kD + col) = __floats2bfloat162_rn(co[j][2] * i1, co[j][3] * i1);
    }
}

// ---------------- fp32 -> bf16 convert ----------------
__global__ void cvt_k(const float* __restrict__ s, bf16* __restrict__ d, int n) {
    int stride = gridDim.x * blockDim.x;
    for (int i = blockIdx.x * blockDim.x + threadIdx.x; i * 4 < n; i += stride) {
        float4 v = *(const float4*)(s + i * 4);
        *(__nv_bfloat162*)(d + i * 4)     = __floats2bfloat162_rn(v.x, v.y);
        *(__nv_bfloat162*)(d + i * 4 + 2) = __floats2bfloat162_rn(v.z, v.w);
    }
}

// ---------------- w12 convert + column interleave ----------------
__global__ void cvt_w12i_k(const float* __restrict__ s, bf16* __restrict__ d) {
    int stride = gridDim.x * blockDim.x;
    int total = kE * kD * 1024;
    for (int g = blockIdx.x * blockDim.x + threadIdx.x; g < total; g += stride) {
        int gi = g & 1023;
        int row = g >> 10;
        int src_col = ((gi >> 1) << 3) + ((gi & 1) ? 4096 : 0);
        const float* sp = s + (size_t)row * 8192 + src_col;
        bf16* dp = d + (size_t)row * 8192 + (gi << 3);
        float4 v0 = *(const float4*)sp;
        float4 v1 = *(const float4*)(sp + 4);
        ((__nv_bfloat162*)dp)[0] = __floats2bfloat162_rn(v0.x, v0.y);
        ((__nv_bfloat162*)dp)[1] = __floats2bfloat162_rn(v0.z, v0.w);
        ((__nv_bfloat162*)dp)[2] = __floats2bfloat162_rn(v1.x, v1.y);
        ((__nv_bfloat162*)dp)[3] = __floats2bfloat162_rn(v1.z, v1.w);
    }
}

// ---------------- RMSNorm ----------------
template <bool DUAL>
__global__ void rmsnorm_k(const float* __restrict__ in, bf16* __restrict__ outb,
                          float* __restrict__ outf) {
    int t = threadIdx.x, row = blockIdx.x;
    const float* r = in + (size_t)row * kD;
    float s = 0.f;
#pragma unroll
    for (int i = 0; i < kD / 256; i++) { float v = r[t + i * 256]; s += v * v; }
    __shared__ float red[256];
    red[t] = s; __syncthreads();
    for (int st = 128; st > 0; st >>= 1) { if (t < st) red[t] += red[t + st]; __syncthreads(); }
    float scale = rsqrtf(red[0] / (float)kD + 1e-6f);
#pragma unroll
    for (int i = 0; i < kD / 256; i++) {
        int d = t + i * 256;
        float v = r[d] * scale;
        outb[(size_t)row * kD + d] = __float2bfloat16_rn(v);
        if (DUAL) outf[(size_t)row * kD + d] = v;
    }
}

// ---------------- Householder Q ----------------
__global__ void hh_k(const float* __restrict__ vs) {
    __shared__ float Q[64][64];
    __shared__ float v[64];
    int j = threadIdx.x;
    for (int i = 0; i < 64; i++) Q[i][j] = (i == j) ? 1.f : 0.f;
    __syncthreads();
    for (int r = 0; r < 32; r++) {
        v[j] = vs[r * 64 + j];
        __syncthreads();
        float vn = 1e-8f;
        for (int i = 0; i < 64; i++) vn += v[i] * v[i];
        float w = 0.f;
        for (int i = 0; i < 64; i++) w += v[i] * Q[i][j];
        float sfac = (2.f / vn) * w;
        for (int i = 0; i < 64; i++) Q[i][j] -= sfac * v[i];
        __syncthreads();
    }
    for (int i = 0; i < 64; i++) g_Qm[i * 64 + j] = Q[i][j];
}

// ---------------- cos/sin table ----------------
__global__ void cossin_k(const float* __restrict__ rope_pos, const float* __restrict__ inv_freq) {
    int s = blockIdx.x, f = threadIdx.x;
    float val = 0.f;
    if (f < 15) { int r = f / 5, jj = f % 5; val = rope_pos[s * 3 + r] * inv_freq[jj]; }
    g_cos[s * 32 + f] = cosf(val);
    g_sin[s * 32 + f] = sinf(val);
}

// ---------------- RnRoPE ----------------
__global__ void rope_k() {
    int s = blockIdx.x;
    int t = threadIdx.x;
    int d = t & 63, isk = t >> 6;
    __shared__ float Qm[64][65];
    __shared__ float xin[2][64], t1s[2][64], rots[2][64], cs[32], sn[32];
    for (int i = t; i < 4096; i += 128) Qm[i >> 6][i & 63] = g_Qm[i];
    if (t < 32) { cs[t] = g_cos[s * 32 + t]; sn[t] = g_sin[s * 32 + t]; }
    for (int i = t; i < 1024; i += 128)
        g_vb[(size_t)s * kD + i] = __float2bfloat16_rn(g_qkv[(size_t)s * 3072 + 2048 + i]);
    __syncthreads();
    for (int h = 0; h < kH; h++) {
        xin[isk][d] = g_qkv[(size_t)s * 3072 + isk * 1024 + h * 64 + d];
        __syncthreads();
        float t1 = 0.f;
#pragma unroll
        for (int e = 0; e < 64; e++) t1 += xin[isk][e] * Qm[d][e];
        t1s[isk][d] = t1; __syncthreads();
        float rot;
        if (d < 32) rot = t1 * cs[d]      - t1s[isk][d + 32] * sn[d];
        else        rot = t1 * cs[d - 32] + t1s[isk][d - 32] * sn[d - 32];
        rots[isk][d] = rot; __syncthreads();
        float o = 0.f;
#pragma unroll
        for (int e = 0; e < 64; e++) o += rots[isk][e] * Qm[e][d];
        if (isk) g_kb[(size_t)s * kD + h * 64 + d] = __float2bfloat16_rn(o);
        else     g_qb[(size_t)s * kD + h * 64 + d] = __float2bfloat16_rn(o * 0.125f);
        __syncthreads();
    }
}

// ---------------- router (fp32 — protects top-k) ----------------
__global__ void init_k() { if (threadIdx.x < kE) g_cnt[threadIdx.x] = 0; }

__global__ void router_k(const float* __restrict__ rw_, const float* __restrict__ rb_) {
    int s = blockIdx.x, t = threadIdx.x;
    float loc[8];
#pragma unroll
    for (int e = 0; e < 8; e++) loc[e] = 0.f;
#pragma unroll
    for (int i = 0; i < 4; i++) {
        int d = t + i * 256;
        float xv = g_xn2[(size_t)s * kD + d];
#pragma unroll
        for (int e = 0; e < 8; e++) loc[e] += xv * rw_[d * 8 + e];
    }
    __shared__ float red[8][256];
#pragma unroll
    for (int e = 0; e < 8; e++) red[e][t] = loc[e];
    __syncthreads();
    for (int st = 128; st > 0; st >>= 1) {
        if (t < st)
#pragma unroll
            for (int e = 0; e < 8; e++) red[e][t] += red[e][t + st];
        __syncthreads();
    }
    if (t == 0) {
        float logit[8], sc[8], sq = 0.f;
        for (int e = 0; e < 8; e++) {
            logit[e] = red[e][0] + rb_[e];
            sq += logit[e] * logit[e];
            sc[e] = 1.f / (1.f + __expf(-logit[e]));
        }
        g_rowsum[s] = sq;
        int idx[3]; float val[3]; bool used[8];
        for (int e = 0; e < 8; e++) used[e] = false;
        float tsum = 0.f;
        for (int k = 0; k < 3; k++) {
            int bi = -1; float bv = -1e30f;
            for (int e = 0; e < 8; e++)
                if (!used[e] && sc[e] > bv) { bv = sc[e]; bi = e; }
            used[bi] = true; idx[k] = bi; val[k] = bv; tsum += bv;
        }
        float inv = 1.f / (tsum + 1e-6f);
        for (int k = 0; k < 3; k++) {
            int e = idx[k];
            int pos = atomicAdd(&g_cnt[e], 1);
            g_list[e * kS + pos] = s;
            g_tokslot[s * 3 + k] = e * kS + pos;
            g_tokw[s * 3 + k] = val[k] * inv;
        }
    }
}

// ---------------- combine ----------------
__global__ void combine_k(float* __restrict__ out) {
    int s = blockIdx.x, t = threadIdx.x;
    float w0 = g_tokw[s * 3 + 0], w1 = g_tokw[s * 3 + 1], w2 = g_tokw[s * 3 + 2];
    size_t y0 = (size_t)g_tokslot[s * 3 + 0] * kD;
    size_t y1 = (size_t)g_tokslot[s * 3 + 1] * kD;
    size_t y2 = (size_t)g_tokslot[s * 3 + 2] * kD;
#pragma unroll
    for (int i = 0; i < 4; i++) {
        int d = t + i * 256;
        float v = g_xmid[(size_t)s * kD + d];
        v += w0 * g_ybuf[y0 + d] + w1 * g_ybuf[y1 + d] + w2 * g_ybuf[y2 + d];
        out[(size_t)s * kD + d] = v;
    }
}

// ---------------- aux loss ----------------
__global__ void aux_k(float* __restrict__ out, int out_size) {
    int t = threadIdx.x;
    float sm = 0.f;
    for (int i = t; i < kS; i += 256) sm += g_rowsum[i];
    __shared__ float red[256];
    red[t] = sm; __syncthreads();
    for (int st = 128; st > 0; st >>= 1) { if (t < st) red[t] += red[t + st]; __syncthreads(); }
    if (t == 0 && out_size > kS * kD)
        out[kS * kD] = 0.01f * red[0] / (float)(kS * kE);
}

// ---------------- host ----------------
static const int kSmemG = NSTG * (128 * AST + 32 * BST2) * 2;  // 75776
static const int kGridP = 296;  // 148 SMs x 2 CTAs

extern "C" void kernel_launch(void* const* d_in, const int* in_sizes, int n_in,
                              void* d_out, int out_size) {
    const float* x        = (const float*)d_in[0];
    const float* rope_pos = (const float*)d_in[1];
    const float* inv_freq = (const float*)d_in[2];
    const float* qkv_w    = (const float*)d_in[3];
    const float* hh_vs    = (const float*)d_in[4];
    const float* out_w    = (const float*)d_in[5];
    const float* gate_w   = (const float*)d_in[6];
    const float* gate_b   = (const float*)d_in[7];
    const float* router_w = (const float*)d_in[8];
    const float* router_b = (const float*)d_in[9];
    const float* w12      = (const float*)d_in[10];
    const float* w3       = (const float*)d_in[11];
    float* outp = (float*)d_out;

    void *p_xnb, *p_qkv, *p_attnb, *p_attnproj, *p_attnprojb, *p_xmid, *p_xn2, *p_xn2b;
    void *p_gbufb, *p_ybuf;
    void *p_wqkvb, *p_woutb, *p_wgateb, *p_w12b, *p_w3b;
    cudaGetSymbolAddress(&p_xnb, g_xnb);
    cudaGetSymbolAddress(&p_qkv, g_qkv);
    cudaGetSymbolAddress(&p_attnb, g_attnb);
    cudaGetSymbolAddress(&p_attnproj, g_attnproj);
    cudaGetSymbolAddress(&p_attnprojb, g_attnprojb);
    cudaGetSymbolAddress(&p_xmid, g_xmid);
    cudaGetSymbolAddress(&p_xn2, g_xn2);
    cudaGetSymbolAddress(&p_xn2b, g_xn2b);
    cudaGetSymbolAddress(&p_gbufb, g_gbufb);
    cudaGetSymbolAddress(&p_ybuf, g_ybuf);
    cudaGetSymbolAddress(&p_wqkvb, g_wqkvb);
    cudaGetSymbolAddress(&p_woutb, g_woutb);
    cudaGetSymbolAddress(&p_wgateb, g_wgateb);
    cudaGetSymbolAddress(&p_w12b, g_w12b);
    cudaGetSymbolAddress(&p_w3b, g_w3b);

    cudaFuncSetAttribute(fattn_k, cudaFuncAttributeMaxDynamicSharedMemorySize, 92160);
    cudaFuncSetAttribute(tgemm_k<0>, cudaFuncAttributeMaxDynamicSharedMemorySize, kSmemG);
    cudaFuncSetAttribute(tgemm_k<1>, cudaFuncAttributeMaxDynamicSharedMemorySize, kSmemG);
    cudaFuncSetAttribute(tgemm_k<2>, cudaFuncAttributeMaxDynamicSharedMemorySize, kSmemG);
    cudaFuncSetAttribute(tgemm_k<3>, cudaFuncAttributeMaxDynamicSharedMemorySize, kSmemG);

    // ---- attention path (index 3 = qkv GEMM, profiled by ncu's fixed sample slot) ----
    rmsnorm_k<false><<<kS, 256>>>(x, (bf16*)p_xnb, nullptr);                 // 0
    cvt_k<<<2048, 256>>>(qkv_w, (bf16*)p_wqkvb, kD * 3 * kD);                // 1
    hh_k<<<1, 64>>>(hh_vs);                                                  // 2
    tgemm_k<0><<<kGridP, 256, kSmemG>>>((const bf16*)p_xnb,                  // 3
        (const bf16*)p_wqkvb, (float*)p_qkv, nullptr, kS, 3 * kD, kD,
        nullptr, nullptr, nullptr, 16, 24, 1);
    cossin_k<<<kS, 32>>>(rope_pos, inv_freq);                                // 4
    rope_k<<<kS, 128>>>();                                                   // 5
    fattn_k<<<dim3(16, 16, 1), 256, 92160>>>();                              // 6
    cvt_k<<<1024, 256>>>(out_w, (bf16*)p_woutb, kD * kD);                    // 7
    tgemm_k<0><<<kGridP, 256, kSmemG>>>((const bf16*)p_attnb,                // 8
        (const bf16*)p_woutb, (float*)p_attnproj, (bf16*)p_attnprojb,
        kS, kD, kD, nullptr, nullptr, nullptr, 16, 8, 1);
    cvt_k<<<1024, 256>>>(gate_w, (bf16*)p_wgateb, kD * kD);                  // 9
    tgemm_k<1><<<kGridP, 256, kSmemG>>>((const bf16*)p_attnprojb,            // 10
        (const bf16*)p_wgateb, (float*)p_xmid, nullptr, kS, kD, kD,
        x, (const float*)p_attnproj, gate_b, 16, 8, 1);

    // ---- MoE path ----
    rmsnorm_k<true><<<kS, 256>>>((const float*)p_xmid, (bf16*)p_xn2b, (float*)p_xn2);
    init_k<<<1, 32>>>();
    router_k<<<kS, 256>>>(router_w, router_b);
    cvt_w12i_k<<<8192, 256>>>(w12, (bf16*)p_w12b);
    tgemm_k<2><<<kGridP, 256, kSmemG>>>((const bf16*)p_xn2b,
        (const bf16*)p_w12b, nullptr, (bf16*)p_gbufb, kS, 2 * kHID, kD,
        nullptr, nullptr, nullptr, 16, 64, 8);
    cvt_k<<<8192, 256>>>(w3, (bf16*)p_w3b, kE * kHID * kD);
    tgemm_k<3><<<kGridP, 256, kSmemG>>>((const bf16*)p_gbufb,
        (const bf16*)p_w3b, (float*)p_ybuf, nullptr, kS, kD, kHID,
        nullptr, nullptr, nullptr, 16, 8, 8);
    combine_k<<<kS, 256>>>(outp);
    aux_k<<<1, 256>>>(outp, out_size);
}

// round 14
// speedup vs baseline: 1.1768x; 1.1768x over previous
#include <cuda_runtime.h>
#include <cuda_bf16.h>
#include <math.h>
#include <stdint.h>

typedef __nv_bfloat16 bf16;

// ---------------- problem constants ----------------
static const int kS   = 2048;
static const int kD   = 1024;
static const int kH   = 16;
static const int kHD  = 64;
static const int kE   = 8;
static const int kHID = 4096;

// ---------------- scratch ----------------
__device__ bf16  g_xnb     [kS*kD];
__device__ float g_qkv     [kS*3*kD];
__device__ bf16  g_qb      [kS*kD];
__device__ bf16  g_kb      [kS*kD];
__device__ bf16  g_vb      [kS*kD];
__device__ float g_Qm      [kHD*kHD];
__device__ float g_cos     [kS*32];
__device__ float g_sin     [kS*32];
__device__ bf16  g_attnb   [kS*kD];
__device__ float g_attnproj[kS*kD];
__device__ bf16  g_attnprojb[kS*kD];
__device__ float g_xmid    [kS*kD];
__device__ float g_xn2     [kS*kD];
__device__ bf16  g_xn2b    [kS*kD];
__device__ float g_rowsum  [kS];
__device__ int   g_cnt     [kE];
__device__ int   g_list    [kE*kS];
__device__ int   g_tokslot [kS*3];
__device__ float g_tokw    [kS*3];
__device__ bf16  g_gbufb   [kE*kS*kHID];
__device__ float g_ybuf    [kE*kS*kD];
// bf16 weights
__device__ bf16  g_wqkvb   [kD*3*kD];
__device__ bf16  g_woutb   [kD*kD];
__device__ bf16  g_wgateb  [kD*kD];
__device__ bf16  g_w12b    [kE*kD*2*kHID];   // column-interleaved [h1 8 | h2 8 | ...]
__device__ bf16  g_w3b     [kE*kHID*kD];

// ================= helpers =================
static __device__ __forceinline__ uint32_t s2u(const void* p) {
    uint32_t a;
    asm("{ .reg .u64 t; cvta.to.shared.u64 t, %1; cvt.u32.u64 %0, t; }" : "=r"(a) : "l"(p));
    return a;
}
#define CPA16(dst, src, sz) \
    asm volatile("cp.async.cg.shared.global [%0], [%1], 16, %2;" :: "r"(dst), "l"(src), "r"(sz))
#define CPA_COMMIT() asm volatile("cp.async.commit_group;" ::: "memory")
#define CPA_WAIT2()  asm volatile("cp.async.wait_group 2;" ::: "memory")
#define CPA_WAIT1()  asm volatile("cp.async.wait_group 1;" ::: "memory")
#define CPA_WAIT0()  asm volatile("cp.async.wait_group 0;" ::: "memory")

#define LDSM4(r0,r1,r2,r3,addr) \
    asm volatile("ldmatrix.sync.aligned.m8n8.x4.shared.b16 {%0,%1,%2,%3}, [%4];" \
        : "=r"(r0),"=r"(r1),"=r"(r2),"=r"(r3) : "r"(addr))
#define LDSM4T(r0,r1,r2,r3,addr) \
    asm volatile("ldmatrix.sync.aligned.m8n8.x4.trans.shared.b16 {%0,%1,%2,%3}, [%4];" \
        : "=r"(r0),"=r"(r1),"=r"(r2),"=r"(r3) : "r"(addr))

#define MMAB(c, a, b0v, b1v) \
    asm volatile("mma.sync.aligned.m16n8k16.row.col.f32.bf16.bf16.f32 " \
        "{%0,%1,%2,%3}, {%4,%5,%6,%7}, {%8,%9}, {%0,%1,%2,%3};" \
        : "+f"((c)[0]),"+f"((c)[1]),"+f"((c)[2]),"+f"((c)[3]) \
        : "r"((a)[0]),"r"((a)[1]),"r"((a)[2]),"r"((a)[3]), "r"(b0v),"r"(b1v))

static __device__ __forceinline__ uint32_t pack2(float a, float b) {
    __nv_bfloat162 t = __floats2bfloat162_rn(a, b);
    return *(uint32_t*)&t;
}

// ================= bf16 mma GEMM: 4-stage pipeline, block 128x128, K-chunk 32 =================
// 8 warps in 2x4; warp tile 64x32. __launch_bounds__(256,2) => <=128 regs, 2 CTAs/SM.
// MODE 0: C = A@B (+ optional bf16 Cb)
// MODE 1: C = X1 + X2 * sigmoid(A@B + bias)
// MODE 2: MoE pass1, fused SwiGLU: Cb = silu(h1)*h2, w12 col-interleaved
// MODE 3: MoE pass2
#define AST 40
#define BST2 136
#define NSTG 4
template <int MODE>
__global__ void __launch_bounds__(256, 2) tgemm_k(
    const bf16* __restrict__ A, const bf16* __restrict__ B, float* __restrict__ C,
    bf16* __restrict__ Cb, int M, int N, int K,
    const float* __restrict__ X1, const float* __restrict__ X2, const float* __restrict__ bias) {
    const int NJ = 4;
    const uint32_t ASTG2 = 128 * AST * 2;
    const uint32_t BSTG2 = 32 * BST2 * 2;

    extern __shared__ bf16 sm_g[];
    bf16* As = sm_g;                       // NSTG stages [128][AST]
    bf16* Bs = sm_g + NSTG * 128 * AST;    // NSTG stages [32][BST2]

    int tid = threadIdx.x;
    int ez = blockIdx.z;
    const int* rowlist = nullptr;
    if (MODE == 2) {
        M = g_cnt[ez]; rowlist = g_list + ez * kS;
        B += (size_t)ez * (size_t)K * (size_t)N;
        Cb += (size_t)ez * (size_t)kS * (size_t)kHID;
    } else if (MODE == 3) {
        M = g_cnt[ez];
        A += (size_t)ez * (size_t)kS * (size_t)K;
        B += (size_t)ez * (size_t)K * (size_t)N;
        C += (size_t)ez * (size_t)kS * (size_t)N;
    }
    int m0 = blockIdx.x * 128, n0 = blockIdx.y * 128;
    if (m0 >= M) return;

    // ---- A load assignment ----
    int arow = tid >> 2, aseg = tid & 3;
    const bf16* aptr0 = A; const bf16* aptr1 = A;
    uint32_t asz0 = 0, asz1 = 0;
    {
        int r0 = m0 + arow, r1 = r0 + 64;
        if (r0 < M) { int gr = (MODE == 2) ? rowlist[r0] : r0; aptr0 = A + (size_t)gr * K + aseg * 8; asz0 = 16; }
        if (r1 < M) { int gr = (MODE == 2) ? rowlist[r1] : r1; aptr1 = A + (size_t)gr * K + aseg * 8; asz1 = 16; }
    }
    uint32_t adst0 = s2u(As + arow * AST + aseg * 8);
    uint32_t adst1 = s2u(As + (arow + 64) * AST + aseg * 8);

    // ---- B load assignment: 2 segs/thread ----
    int brow = tid >> 4, bseg = tid & 15;
    uint32_t bdst0 = s2u(Bs + brow * BST2 + bseg * 8);
    uint32_t bdst1 = s2u(Bs + (brow + 16) * BST2 + bseg * 8);
    const bf16* bbase = B + n0;

    auto load_chunk = [&](int c, int st) {
        CPA16(adst0 + st * ASTG2, aptr0 + c * 32, asz0);
        CPA16(adst1 + st * ASTG2, aptr1 + c * 32, asz1);
        CPA16(bdst0 + st * BSTG2, bbase + (size_t)(c * 32 + brow) * N + bseg * 8, 16u);
        CPA16(bdst1 + st * BSTG2, bbase + (size_t)(c * 32 + brow + 16) * N + bseg * 8, 16u);
    };

    // ---- warp tiling ----
    int wid = tid >> 5, lane = tid & 31;
    int wm = (wid >> 2) * 64, wn = (wid & 3) * 32;
    int l15 = lane & 15, lh = (lane >> 4) * 8;

    uint32_t abase   = s2u(As) + ((wm + l15) * AST + lh) * 2;
    uint32_t bbase_s = s2u(Bs) + (l15 * BST2 + wn + lh) * 2;

    float c[4][NJ][4];
#pragma unroll
    for (int i = 0; i < 4; i++)
#pragma unroll
        for (int j = 0; j < NJ; j++)
#pragma unroll
            for (int r = 0; r < 4; r++) c[i][j][r] = 0.f;

    int nch = K / 32;
    load_chunk(0, 0); CPA_COMMIT();
    load_chunk(1, 1); CPA_COMMIT();
    load_chunk(2, 2); CPA_COMMIT();

    for (int cc = 0; cc < nch; cc++) {
        int st = cc % NSTG;
        CPA_WAIT2();          // chunk cc arrived (<=2 younger groups pending)
        __syncthreads();      // stage (cc+3)%NSTG == (cc-1)%NSTG is free
        if (cc + 3 < nch) load_chunk(cc + 3, (cc + 3) % NSTG);
        CPA_COMMIT();
#pragma unroll
        for (int kk = 0; kk < 32; kk += 16) {
            uint32_t af[4][4];
#pragma unroll
            for (int mi = 0; mi < 4; mi++)
                LDSM4(af[mi][0], af[mi][1], af[mi][2], af[mi][3],
                      abase + st * ASTG2 + (mi * 16 * AST + kk) * 2);
            uint32_t bq[8];
            LDSM4T(bq[0], bq[1], bq[2], bq[3], bbase_s + st * BSTG2 + (kk * BST2) * 2);
            LDSM4T(bq[4], bq[5], bq[6], bq[7], bbase_s + st * BSTG2 + (kk * BST2 + 16) * 2);
#pragma unroll
            for (int mi = 0; mi < 4; mi++)
#pragma unroll
                for (int nj = 0; nj < NJ; nj++)
                    MMAB(c[mi][nj], af[mi], bq[nj * 2], bq[nj * 2 + 1]);
        }
    }

    __syncthreads();
    int grp = lane >> 2, qid = lane & 3;
#pragma unroll
    for (int mi = 0; mi < 4; mi++) {
#pragma unroll
        for (int half = 0; half < 2; half++) {
            int row = m0 + wm + mi * 16 + grp + half * 8;
            if (row >= M) continue;
            if (MODE == 2) {
                size_t rb2 = (size_t)row * kHID;
#pragma unroll
                for (int njp = 0; njp < NJ; njp += 2) {
                    int cb = n0 + wn + njp * 8 + qid * 2;
                    int oc = ((cb >> 4) << 3) + (cb & 7);
                    float h1a = c[mi][njp][half * 2], h1b = c[mi][njp][half * 2 + 1];
                    float h2a = c[mi][njp + 1][half * 2], h2b = c[mi][njp + 1][half * 2 + 1];
                    float g0 = h1a / (1.f + __expf(-h1a)) * h2a;
                    float g1 = h1b / (1.f + __expf(-h1b)) * h2b;
                    *(__nv_bfloat162*)(Cb + rb2 + oc) = __floats2bfloat162_rn(g0, g1);
                }
                continue;
            }
            size_t rb = (size_t)row * N;
#pragma unroll
            for (int nj = 0; nj < NJ; nj++) {
                int col = n0 + wn + nj * 8 + qid * 2;
                float v0 = c[mi][nj][half * 2 + 0];
                float v1 = c[mi][nj][half * 2 + 1];
                if (MODE == 1) {
                    float g0 = 1.f / (1.f + __expf(-(v0 + bias[col])));
                    float g1 = 1.f / (1.f + __expf(-(v1 + bias[col + 1])));
                    float o0 = X1[rb + col] + X2[rb + col] * g0;
                    float o1 = X1[rb + col + 1] + X2[rb + col + 1] * g1;
                    *(float2*)(C + rb + col) = make_float2(o0, o1);
                } else {
                    *(float2*)(C + rb + col) = make_float2(v0, v1);
                    if (MODE == 0 && Cb)
                        *(__nv_bfloat162*)(Cb + rb + col) = __floats2bfloat162_rn(v0, v1);
                }
            }
        }
    }
}

// ================= bf16 mma flash attention: 128-q x 64-kv tiles, 2 CTAs/SM =================
// smem: Q[128][72] + 2x K[64][72] + 2x V[64][72] = 55296 B; __launch_bounds__(256,2).
__global__ void __launch_bounds__(256, 2) fattn_k() {
    extern __shared__ char sm_[];
    bf16* Qs = (bf16*)sm_;              // [128][72]
    bf16* Ks = Qs + 128 * 72;           // 2 x [64][72]
    bf16* Vs = Ks + 2 * 64 * 72;        // 2 x [64][72]
    int h = blockIdx.y, q0 = blockIdx.x * 128;
    int tid = threadIdx.x, wid = tid >> 5, lane = tid & 31;
    int l15 = lane & 15, lh = (lane >> 4) * 8;
    int grp = lane >> 2, qid = lane & 3;

    {   // Q preload (grouped with KV tile 0)
        int r = tid >> 1, sb = (tid & 1) * 4;
        const bf16* src = g_qb + (size_t)(q0 + r) * kD + h * 64 + sb * 8;
        uint32_t dst = s2u(Qs + r * 72 + sb * 8);
#pragma unroll
        for (int j = 0; j < 4; j++) CPA16(dst + j * 16, src + j * 8, 16u);
    }
    auto loadKV = [&](int it, int buf) {
        int k0 = it * 64;
        int r = tid >> 2, sb = (tid & 3) * 2;   // 64 rows x 2 16B-segs per thread
        const bf16* ks = g_kb + (size_t)(k0 + r) * kD + h * 64 + sb * 8;
        const bf16* vs = g_vb + (size_t)(k0 + r) * kD + h * 64 + sb * 8;
        uint32_t kd = s2u(Ks + buf * 4608 + r * 72 + sb * 8);
        uint32_t vd = s2u(Vs + buf * 4608 + r * 72 + sb * 8);
        CPA16(kd, ks, 16u);       CPA16(kd + 16, ks + 8, 16u);
        CPA16(vd, vs, 16u);       CPA16(vd + 16, vs + 8, 16u);
    };
    loadKV(0, 0); CPA_COMMIT();

    uint32_t qf[4][4];
    float m0 = -1e30f, m1 = -1e30f, l0 = 0.f, l1 = 0.f;
    float co[8][4];
#pragma unroll
    for (int j = 0; j < 8; j++)
#pragma unroll
        for (int r = 0; r < 4; r++) co[j][r] = 0.f;

    for (int it = 0; it < 32; it++) {
        int buf = it & 1;
        if (it + 1 < 32) { loadKV(it + 1, buf ^ 1); CPA_COMMIT(); CPA_WAIT1(); }
        else CPA_WAIT0();
        __syncthreads();
        if (it == 0) {
            uint32_t qb_ = s2u(Qs) + ((wid * 16 + l15) * 72 + lh) * 2;
#pragma unroll
            for (int kk4 = 0; kk4 < 4; kk4++)
                LDSM4(qf[kk4][0], qf[kk4][1], qf[kk4][2], qf[kk4][3], qb_ + kk4 * 32);
        }
        // ---- S = Q K^T (64 keys) ----
        float cs[8][4];
#pragma unroll
        for (int ng = 0; ng < 8; ng++)
#pragma unroll
            for (int r = 0; r < 4; r++) cs[ng][r] = 0.f;
        uint32_t kb_ = s2u(Ks) + buf * 9216;
        int krow = (lane & 7) + ((lane >> 4) << 3);
        int kofs = ((lane >> 3) & 1) << 3;
#pragma unroll
        for (int kk4 = 0; kk4 < 4; kk4++) {
#pragma unroll
            for (int nb = 0; nb < 4; nb++) {
                uint32_t b0, b1, b2, b3;
                LDSM4(b0, b1, b2, b3, kb_ + ((nb * 16 + krow) * 72 + kk4 * 16 + kofs) * 2);
                MMAB(cs[2 * nb], qf[kk4], b0, b1);
                MMAB(cs[2 * nb + 1], qf[kk4], b2, b3);
            }
        }
        // ---- online softmax ----
        float mx0 = -1e30f, mx1 = -1e30f;
#pragma unroll
        for (int ng = 0; ng < 8; ng++) {
            mx0 = fmaxf(mx0, fmaxf(cs[ng][0], cs[ng][1]));
            mx1 = fmaxf(mx1, fmaxf(cs[ng][2], cs[ng][3]));
        }
        mx0 = fmaxf(mx0, __shfl_xor_sync(0xffffffffu, mx0, 1));
        mx0 = fmaxf(mx0, __shfl_xor_sync(0xffffffffu, mx0, 2));
        mx1 = fmaxf(mx1, __shfl_xor_sync(0xffffffffu, mx1, 1));
        mx1 = fmaxf(mx1, __shfl_xor_sync(0xffffffffu, mx1, 2));
        float nm0 = fmaxf(m0, mx0), nm1 = fmaxf(m1, mx1);
        float a0 = __expf(m0 - nm0), a1 = __expf(m1 - nm1);
        l0 *= a0; l1 *= a1;
#pragma unroll
        for (int j = 0; j < 8; j++) {
            co[j][0] *= a0; co[j][1] *= a0; co[j][2] *= a1; co[j][3] *= a1;
        }
#pragma unroll
        for (int ng = 0; ng < 8; ng++) {
            float p0 = __expf(cs[ng][0] - nm0), p1 = __expf(cs[ng][1] - nm0);
            float p2 = __expf(cs[ng][2] - nm1), p3 = __expf(cs[ng][3] - nm1);
            l0 += p0 + p1; l1 += p2 + p3;
            cs[ng][0] = p0; cs[ng][1] = p1; cs[ng][2] = p2; cs[ng][3] = p3;
        }
        m0 = nm0; m1 = nm1;
        // ---- P fragments (register-only) ----
        uint32_t pf[4][4];
#pragma unroll
        for (int kg = 0; kg < 4; kg++) {
            pf[kg][0] = pack2(cs[2 * kg][0], cs[2 * kg][1]);
            pf[kg][1] = pack2(cs[2 * kg][2], cs[2 * kg][3]);
            pf[kg][2] = pack2(cs[2 * kg + 1][0], cs[2 * kg + 1][1]);
            pf[kg][3] = pack2(cs[2 * kg + 1][2], cs[2 * kg + 1][3]);
        }
        // ---- O += P V ----
        uint32_t vb_ = s2u(Vs) + buf * 9216;
#pragma unroll
        for (int kg = 0; kg < 4; kg++) {
#pragma unroll
            for (int vb = 0; vb < 4; vb++) {
                uint32_t t0, t1, t2, t3;
                LDSM4T(t0, t1, t2, t3, vb_ + ((kg * 16 + l15) * 72 + vb * 16 + lh) * 2);
                MMAB(co[2 * vb], pf[kg], t0, t1);
                MMAB(co[2 * vb + 1], pf[kg], t2, t3);
            }
        }
        __syncthreads();
    }
    l0 += __shfl_xor_sync(0xffffffffu, l0, 1);
    l0 += __shfl_xor_sync(0xffffffffu, l0, 2);
    l1 += __shfl_xor_sync(0xffffffffu, l1, 1);
    l1 += __shfl_xor_sync(0xffffffffu, l1, 2);
    float i0 = 1.f / l0, i1 = 1.f / l1;
    int r0 = q0 + wid * 16 + grp, r1 = r0 + 8;
#pragma unroll
    for (int j = 0; j < 8; j++) {
        int col = h * 64 + j * 8 + qid * 2;
        *(__nv_bfloat162*)(g_attnb + (size_t)r0 * kD + col) = __floats2bfloat162_rn(co[j][0] * i0, co[j][1] * i0);
        *(__nv_bfloat162*)(g_attnb + (size_t)r1 * kD + col) = __floats2bfloat162_rn(co[j][2] * i1, co[j][3] * i1);
    }
}

// ---------------- fp32 -> bf16 convert ----------------
__global__ void cvt_k(const float* __restrict__ s, bf16* __restrict__ d, int n) {
    int stride = gridDim.x * blockDim.x;
    for (int i = blockIdx.x * blockDim.x + threadIdx.x; i * 4 < n; i += stride) {
        float4 v = *(const float4*)(s + i * 4);
        *(__nv_bfloat162*)(d + i * 4)     = __floats2bfloat162_rn(v.x, v.y);
        *(__nv_bfloat162*)(d + i * 4 + 2) = __floats2bfloat162_rn(v.z, v.w);
    }
}

// ---------------- w12 convert + column interleave ----------------
__global__ void cvt_w12i_k(const float* __restrict__ s, bf16* __restrict__ d) {
    int stride = gridDim.x * blockDim.x;
    int total = kE * kD * 1024;
    for (int g = blockIdx.x * blockDim.x + threadIdx.x; g < total; g += stride) {
        int gi = g & 1023;
        int row = g >> 10;
        int src_col = ((gi >> 1) << 3) + ((gi & 1) ? 4096 : 0);
        const float* sp = s + (size_t)row * 8192 + src_col;
        bf16* dp = d + (size_t)row * 8192 + (gi << 3);
        float4 v0 = *(const float4*)sp;
        float4 v1 = *(const float4*)(sp + 4);
        ((__nv_bfloat162*)dp)[0] = __floats2bfloat162_rn(v0.x, v0.y);
        ((__nv_bfloat162*)dp)[1] = __floats2bfloat162_rn(v0.z, v0.w);
        ((__nv_bfloat162*)dp)[2] = __floats2bfloat162_rn(v1.x, v1.y);
        ((__nv_bfloat162*)dp)[3] = __floats2bfloat162_rn(v1.z, v1.w);
    }
}

// ---------------- RMSNorm ----------------
template <bool DUAL>
__global__ void rmsnorm_k(const float* __restrict__ in, bf16* __restrict__ outb,
                          float* __restrict__ outf) {
    int t = threadIdx.x, row = blockIdx.x;
    const float* r = in + (size_t)row * kD;
    float s = 0.f;
#pragma unroll
    for (int i = 0; i < kD / 256; i++) { float v = r[t + i * 256]; s += v * v; }
    __shared__ float red[256];
    red[t] = s; __syncthreads();
    for (int st = 128; st > 0; st >>= 1) { if (t < st) red[t] += red[t + st]; __syncthreads(); }
    float scale = rsqrtf(red[0] / (float)kD + 1e-6f);
#pragma unroll
    for (int i = 0; i < kD / 256; i++) {
        int d = t + i * 256;
        float v = r[d] * scale;
        outb[(size_t)row * kD + d] = __float2bfloat16_rn(v);
        if (DUAL) outf[(size_t)row * kD + d] = v;
    }
}

// ---------------- Householder Q ----------------
__global__ void hh_k(const float* __restrict__ vs) {
    __shared__ float Q[64][64];
    __shared__ float v[64];
    int j = threadIdx.x;
    for (int i = 0; i < 64; i++) Q[i][j] = (i == j) ? 1.f : 0.f;
    __syncthreads();
    for (int r = 0; r < 32; r++) {
        v[j] = vs[r * 64 + j];
        __syncthreads();
        float vn = 1e-8f;
        for (int i = 0; i < 64; i++) vn += v[i] * v[i];
        float w = 0.f;
        for (int i = 0; i < 64; i++) w += v[i] * Q[i][j];
        float sfac = (2.f / vn) * w;
        for (int i = 0; i < 64; i++) Q[i][j] -= sfac * v[i];
        __syncthreads();
    }
    for (int i = 0; i < 64; i++) g_Qm[i * 64 + j] = Q[i][j];
}

// ---------------- cos/sin table ----------------
__global__ void cossin_k(const float* __restrict__ rope_pos, const float* __restrict__ inv_freq) {
    int s = blockIdx.x, f = threadIdx.x;
    float val = 0.f;
    if (f < 15) { int r = f / 5, jj = f % 5; val = rope_pos[s * 3 + r] * inv_freq[jj]; }
    g_cos[s * 32 + f] = cosf(val);
    g_sin[s * 32 + f] = sinf(val);
}

// ---------------- RnRoPE ----------------
__global__ void rope_k() {
    int s = blockIdx.x;
    int t = threadIdx.x;
    int d = t & 63, isk = t >> 6;
    __shared__ float Qm[64][65];
    __shared__ float xin[2][64], t1s[2][64], rots[2][64], cs[32], sn[32];
    for (int i = t; i < 4096; i += 128) Qm[i >> 6][i & 63] = g_Qm[i];
    if (t < 32) { cs[t] = g_cos[s * 32 + t]; sn[t] = g_sin[s * 32 + t]; }
    for (int i = t; i < 1024; i += 128)
        g_vb[(size_t)s * kD + i] = __float2bfloat16_rn(g_qkv[(size_t)s * 3072 + 2048 + i]);
    __syncthreads();
    for (int h = 0; h < kH; h++) {
        xin[isk][d] = g_qkv[(size_t)s * 3072 + isk * 1024 + h * 64 + d];
        __syncthreads();
        float t1 = 0.f;
#pragma unroll
        for (int e = 0; e < 64; e++) t1 += xin[isk][e] * Qm[d][e];
        t1s[isk][d] = t1; __syncthreads();
        float rot;
        if (d < 32) rot = t1 * cs[d]      - t1s[isk][d + 32] * sn[d];
        else        rot = t1 * cs[d - 32] + t1s[isk][d - 32] * sn[d - 32];
        rots[isk][d] = rot; __syncthreads();
        float o = 0.f;
#pragma unroll
        for (int e = 0; e < 64; e++) o += rots[isk][e] * Qm[e][d];
        if (isk) g_kb[(size_t)s * kD + h * 64 + d] = __float2bfloat16_rn(o);
        else     g_qb[(size_t)s * kD + h * 64 + d] = __float2bfloat16_rn(o * 0.125f);
        __syncthreads();
    }
}

// ---------------- router (fp32 — protects top-k) ----------------
__global__ void init_k() { if (threadIdx.x < kE) g_cnt[threadIdx.x] = 0; }

__global__ void router_k(const float* __restrict__ rw_, const float* __restrict__ rb_) {
    int s = blockIdx.x, t = threadIdx.x;
    float loc[8];
#pragma unroll
    for (int e = 0; e < 8; e++) loc[e] = 0.f;
#pragma unroll
    for (int i = 0; i < 4; i++) {
        int d = t + i * 256;
        float xv = g_xn2[(size_t)s * kD + d];
#pragma unroll
        for (int e = 0; e < 8; e++) loc[e] += xv * rw_[d * 8 + e];
    }
    __shared__ float red[8][256];
#pragma unroll
    for (int e = 0; e < 8; e++) red[e][t] = loc[e];
    __syncthreads();
    for (int st = 128; st > 0; st >>= 1) {
        if (t < st)
#pragma unroll
            for (int e = 0; e < 8; e++) red[e][t] += red[e][t + st];
        __syncthreads();
    }
    if (t == 0) {
        float logit[8], sc[8], sq = 0.f;
        for (int e = 0; e < 8; e++) {
            logit[e] = red[e][0] + rb_[e];
            sq += logit[e] * logit[e];
            sc[e] = 1.f / (1.f + __expf(-logit[e]));
        }
        g_rowsum[s] = sq;
        int idx[3]; float val[3]; bool used[8];
        for (int e = 0; e < 8; e++) used[e] = false;
        float tsum = 0.f;
        for (int k = 0; k < 3; k++) {
            int bi = -1; float bv = -1e30f;
            for (int e = 0; e < 8; e++)
                if (!used[e] && sc[e] > bv) { bv = sc[e]; bi = e; }
            used[bi] = true; idx[k] = bi; val[k] = bv; tsum += bv;
        }
        float inv = 1.f / (tsum + 1e-6f);
        for (int k = 0; k < 3; k++) {
            int e = idx[k];
            int pos = atomicAdd(&g_cnt[e], 1);
            g_list[e * kS + pos] = s;
            g_tokslot[s * 3 + k] = e * kS + pos;
            g_tokw[s * 3 + k] = val[k] * inv;
        }
    }
}

// ---------------- combine ----------------
__global__ void combine_k(float* __restrict__ out) {
    int s = blockIdx.x, t = threadIdx.x;
    float w0 = g_tokw[s * 3 + 0], w1 = g_tokw[s * 3 + 1], w2 = g_tokw[s * 3 + 2];
    size_t y0 = (size_t)g_tokslot[s * 3 + 0] * kD;
    size_t y1 = (size_t)g_tokslot[s * 3 + 1] * kD;
    size_t y2 = (size_t)g_tokslot[s * 3 + 2] * kD;
#pragma unroll
    for (int i = 0; i < 4; i++) {
        int d = t + i * 256;
        float v = g_xmid[(size_t)s * kD + d];
        v += w0 * g_ybuf[y0 + d] + w1 * g_ybuf[y1 + d] + w2 * g_ybuf[y2 + d];
        out[(size_t)s * kD + d] = v;
    }
}

// ---------------- aux loss ----------------
__global__ void aux_k(float* __restrict__ out, int out_size) {
    int t = threadIdx.x;
    float sm = 0.f;
    for (int i = t; i < kS; i += 256) sm += g_rowsum[i];
    __shared__ float red[256];
    red[t] = sm; __syncthreads();
    for (int st = 128; st > 0; st >>= 1) { if (t < st) red[t] += red[t + st]; __syncthreads(); }
    if (t == 0 && out_size > kS * kD)
        out[kS * kD] = 0.01f * red[0] / (float)(kS * kE);
}

// ---------------- host ----------------
static const int kSmemG = NSTG * (128 * AST + 32 * BST2) * 2;  // 75776
static const int kSmemA = (128 * 72 + 4 * 64 * 72) * 2;        // 55296

extern "C" void kernel_launch(void* const* d_in, const int* in_sizes, int n_in,
                              void* d_out, int out_size) {
    const float* x        = (const float*)d_in[0];
    const float* rope_pos = (const float*)d_in[1];
    const float* inv_freq = (const float*)d_in[2];
    const float* qkv_w    = (const float*)d_in[3];
    const float* hh_vs    = (const float*)d_in[4];
    const float* out_w    = (const float*)d_in[5];
    const float* gate_w   = (const float*)d_in[6];
    const float* gate_b   = (const float*)d_in[7];
    const float* router_w = (const float*)d_in[8];
    const float* router_b = (const float*)d_in[9];
    const float* w12      = (const float*)d_in[10];
    const float* w3       = (const float*)d_in[11];
    float* outp = (float*)d_out;

    void *p_xnb, *p_qkv, *p_attnb, *p_attnproj, *p_attnprojb, *p_xmid, *p_xn2, *p_xn2b;
    void *p_gbufb, *p_ybuf;
    void *p_wqkvb, *p_woutb, *p_wgateb, *p_w12b, *p_w3b;
    cudaGetSymbolAddress(&p_xnb, g_xnb);
    cudaGetSymbolAddress(&p_qkv, g_qkv);
    cudaGetSymbolAddress(&p_attnb, g_attnb);
    cudaGetSymbolAddress(&p_attnproj, g_attnproj);
    cudaGetSymbolAddress(&p_attnprojb, g_attnprojb);
    cudaGetSymbolAddress(&p_xmid, g_xmid);
    cudaGetSymbolAddress(&p_xn2, g_xn2);
    cudaGetSymbolAddress(&p_xn2b, g_xn2b);
    cudaGetSymbolAddress(&p_gbufb, g_gbufb);
    cudaGetSymbolAddress(&p_ybuf, g_ybuf);
    cudaGetSymbolAddress(&p_wqkvb, g_wqkvb);
    cudaGetSymbolAddress(&p_woutb, g_woutb);
    cudaGetSymbolAddress(&p_wgateb, g_wgateb);
    cudaGetSymbolAddress(&p_w12b, g_w12b);
    cudaGetSymbolAddress(&p_w3b, g_w3b);

    cudaFuncSetAttribute(fattn_k, cudaFuncAttributeMaxDynamicSharedMemorySize, kSmemA);
    cudaFuncSetAttribute(tgemm_k<0>, cudaFuncAttributeMaxDynamicSharedMemorySize, kSmemG);
    cudaFuncSetAttribute(tgemm_k<1>, cudaFuncAttributeMaxDynamicSharedMemorySize, kSmemG);
    cudaFuncSetAttribute(tgemm_k<2>, cudaFuncAttributeMaxDynamicSharedMemorySize, kSmemG);
    cudaFuncSetAttribute(tgemm_k<3>, cudaFuncAttributeMaxDynamicSharedMemorySize, kSmemG);

    // ---- attention path (index 3 = qkv GEMM, profiled by ncu's fixed sample slot) ----
    rmsnorm_k<false><<<kS, 256>>>(x, (bf16*)p_xnb, nullptr);                 // 0
    cvt_k<<<2048, 256>>>(qkv_w, (bf16*)p_wqkvb, kD * 3 * kD);                // 1
    hh_k<<<1, 64>>>(hh_vs);                                                  // 2
    tgemm_k<0><<<dim3(16, 24, 1), 256, kSmemG>>>((const bf16*)p_xnb,         // 3
        (const bf16*)p_wqkvb, (float*)p_qkv, nullptr, kS, 3 * kD, kD,
        nullptr, nullptr, nullptr);
    cossin_k<<<kS, 32>>>(rope_pos, inv_freq);                                // 4
    rope_k<<<kS, 128>>>();                                                   // 5
    fattn_k<<<dim3(16, 16, 1), 256, kSmemA>>>();                             // 6
    cvt_k<<<1024, 256>>>(out_w, (bf16*)p_woutb, kD * kD);                    // 7
    tgemm_k<0><<<dim3(16, 8, 1), 256, kSmemG>>>((const bf16*)p_attnb,        // 8
        (const bf16*)p_woutb, (float*)p_attnproj, (bf16*)p_attnprojb,
        kS, kD, kD, nullptr, nullptr, nullptr);
    cvt_k<<<1024, 256>>>(gate_w, (bf16*)p_wgateb, kD * kD);                  // 9
    tgemm_k<1><<<dim3(16, 8, 1), 256, kSmemG>>>((const bf16*)p_attnprojb,    // 10
        (const bf16*)p_wgateb, (float*)p_xmid, nullptr, kS, kD, kD,
        x, (const float*)p_attnproj, gate_b);

    // ---- MoE path ----
    rmsnorm_k<true><<<kS, 256>>>((const float*)p_xmid, (bf16*)p_xn2b, (float*)p_xn2);
    init_k<<<1, 32>>>();
    router_k<<<kS, 256>>>(router_w, router_b);
    cvt_w12i_k<<<8192, 256>>>(w12, (bf16*)p_w12b);
    tgemm_k<2><<<dim3(16, 64, 8), 256, kSmemG>>>((const bf16*)p_xn2b,
        (const bf16*)p_w12b, nullptr, (bf16*)p_gbufb, kS, 2 * kHID, kD,
        nullptr, nullptr, nullptr);
    cvt_k<<<8192, 256>>>(w3, (bf16*)p_w3b, kE * kHID * kD);
    tgemm_k<3><<<dim3(16, 8, 8), 256, kSmemG>>>((const bf16*)p_gbufb,
        (const bf16*)p_w3b, (float*)p_ybuf, nullptr, kS, kD, kHID,
        nullptr, nullptr, nullptr);
    combine_k<<<kS, 256>>>(outp);
    aux_k<<<1, 256>>>(outp, out_size);
}

// round 15
// speedup vs baseline: 1.2245x; 1.0405x over previous
#include <cuda_runtime.h>
#include <cuda_bf16.h>
#include <math.h>
#include <stdint.h>

typedef __nv_bfloat16 bf16;

// ---------------- problem constants ----------------
static const int kS   = 2048;
static const int kD   = 1024;
static const int kH   = 16;
static const int kHD  = 64;
static const int kE   = 8;
static const int kHID = 4096;

// ---------------- scratch ----------------
__device__ bf16  g_xnb     [kS*kD];
__device__ float g_qkv     [kS*3*kD];
__device__ bf16  g_qb      [kS*kD];
__device__ bf16  g_kb      [kS*kD];
__device__ bf16  g_vb      [kS*kD];
__device__ float g_Qm      [kHD*kHD];
__device__ float g_cos     [kS*32];
__device__ float g_sin     [kS*32];
__device__ bf16  g_attnb   [kS*kD];
__device__ float g_attnproj[kS*kD];
__device__ bf16  g_attnprojb[kS*kD];
__device__ float g_xmid    [kS*kD];
__device__ float g_xn2     [kS*kD];
__device__ bf16  g_xn2b    [kS*kD];
__device__ float g_rowsum  [kS];
__device__ int   g_cnt     [kE];
__device__ int   g_list    [kE*kS];
__device__ int   g_tokslot [kS*3];
__device__ float g_tokw    [kS*3];
__device__ bf16  g_gbufb   [kE*kS*kHID];
__device__ float g_ybuf    [kE*kS*kD];
// bf16 weights
__device__ bf16  g_wqkvb   [kD*3*kD];
__device__ bf16  g_woutb   [kD*kD];
__device__ bf16  g_wgateb  [kD*kD];
__device__ bf16  g_w12b    [kE*kD*2*kHID];   // column-interleaved [h1 8 | h2 8 | ...]
__device__ bf16  g_w3b     [kE*kHID*kD];

// ================= helpers =================
static __device__ __forceinline__ uint32_t s2u(const void* p) {
    uint32_t a;
    asm("{ .reg .u64 t; cvta.to.shared.u64 t, %1; cvt.u32.u64 %0, t; }" : "=r"(a) : "l"(p));
    return a;
}
#define CPA16(dst, src, sz) \
    asm volatile("cp.async.cg.shared.global [%0], [%1], 16, %2;" :: "r"(dst), "l"(src), "r"(sz))
#define CPA_COMMIT() asm volatile("cp.async.commit_group;" ::: "memory")
#define CPA_WAIT2()  asm volatile("cp.async.wait_group 2;" ::: "memory")
#define CPA_WAIT1()  asm volatile("cp.async.wait_group 1;" ::: "memory")
#define CPA_WAIT0()  asm volatile("cp.async.wait_group 0;" ::: "memory")

#define LDSM4(r0,r1,r2,r3,addr) \
    asm volatile("ldmatrix.sync.aligned.m8n8.x4.shared.b16 {%0,%1,%2,%3}, [%4];" \
        : "=r"(r0),"=r"(r1),"=r"(r2),"=r"(r3) : "r"(addr))
#define LDSM4T(r0,r1,r2,r3,addr) \
    asm volatile("ldmatrix.sync.aligned.m8n8.x4.trans.shared.b16 {%0,%1,%2,%3}, [%4];" \
        : "=r"(r0),"=r"(r1),"=r"(r2),"=r"(r3) : "r"(addr))

#define MMAB(c, a, b0v, b1v) \
    asm volatile("mma.sync.aligned.m16n8k16.row.col.f32.bf16.bf16.f32 " \
        "{%0,%1,%2,%3}, {%4,%5,%6,%7}, {%8,%9}, {%0,%1,%2,%3};" \
        : "+f"((c)[0]),"+f"((c)[1]),"+f"((c)[2]),"+f"((c)[3]) \
        : "r"((a)[0]),"r"((a)[1]),"r"((a)[2]),"r"((a)[3]), "r"(b0v),"r"(b1v))

static __device__ __forceinline__ uint32_t pack2(float a, float b) {
    __nv_bfloat162 t = __floats2bfloat162_rn(a, b);
    return *(uint32_t*)&t;
}

// ================= bf16 mma GEMM: 4-stage pipeline, block 128x128, K-chunk 32 =================
// 8 warps in 2x4; warp tile 64x32. __launch_bounds__(256,2) => <=128 regs, 2 CTAs/SM.
// MODE 0: C = A@B (+ optional bf16 Cb)
// MODE 1: C = X1 + X2 * sigmoid(A@B + bias)
// MODE 2: MoE pass1, fused SwiGLU: Cb = silu(h1)*h2, w12 col-interleaved
// MODE 3: MoE pass2
#define AST 40
#define BST2 136
#define NSTG 4
template <int MODE>
__global__ void __launch_bounds__(256, 2) tgemm_k(
    const bf16* __restrict__ A, const bf16* __restrict__ B, float* __restrict__ C,
    bf16* __restrict__ Cb, int M, int N, int K,
    const float* __restrict__ X1, const float* __restrict__ X2, const float* __restrict__ bias) {
    const int NJ = 4;
    const uint32_t ASTG2 = 128 * AST * 2;
    const uint32_t BSTG2 = 32 * BST2 * 2;

    extern __shared__ bf16 sm_g[];
    bf16* As = sm_g;                       // NSTG stages [128][AST]
    bf16* Bs = sm_g + NSTG * 128 * AST;    // NSTG stages [32][BST2]

    int tid = threadIdx.x;
    int ez = blockIdx.z;
    const int* rowlist = nullptr;
    if (MODE == 2) {
        M = g_cnt[ez]; rowlist = g_list + ez * kS;
        B += (size_t)ez * (size_t)K * (size_t)N;
        Cb += (size_t)ez * (size_t)kS * (size_t)kHID;
    } else if (MODE == 3) {
        M = g_cnt[ez];
        A += (size_t)ez * (size_t)kS * (size_t)K;
        B += (size_t)ez * (size_t)K * (size_t)N;
        C += (size_t)ez * (size_t)kS * (size_t)N;
    }
    int m0 = blockIdx.x * 128, n0 = blockIdx.y * 128;
    if (m0 >= M) return;

    // ---- A load assignment ----
    int arow = tid >> 2, aseg = tid & 3;
    const bf16* aptr0 = A; const bf16* aptr1 = A;
    uint32_t asz0 = 0, asz1 = 0;
    {
        int r0 = m0 + arow, r1 = r0 + 64;
        if (r0 < M) { int gr = (MODE == 2) ? rowlist[r0] : r0; aptr0 = A + (size_t)gr * K + aseg * 8; asz0 = 16; }
        if (r1 < M) { int gr = (MODE == 2) ? rowlist[r1] : r1; aptr1 = A + (size_t)gr * K + aseg * 8; asz1 = 16; }
    }
    uint32_t adst0 = s2u(As + arow * AST + aseg * 8);
    uint32_t adst1 = s2u(As + (arow + 64) * AST + aseg * 8);

    // ---- B load assignment: 2 segs/thread ----
    int brow = tid >> 4, bseg = tid & 15;
    uint32_t bdst0 = s2u(Bs + brow * BST2 + bseg * 8);
    uint32_t bdst1 = s2u(Bs + (brow + 16) * BST2 + bseg * 8);
    const bf16* bbase = B + n0;

    auto load_chunk = [&](int c, int st) {
        CPA16(adst0 + st * ASTG2, aptr0 + c * 32, asz0);
        CPA16(adst1 + st * ASTG2, aptr1 + c * 32, asz1);
        CPA16(bdst0 + st * BSTG2, bbase + (size_t)(c * 32 + brow) * N + bseg * 8, 16u);
        CPA16(bdst1 + st * BSTG2, bbase + (size_t)(c * 32 + brow + 16) * N + bseg * 8, 16u);
    };

    // ---- warp tiling ----
    int wid = tid >> 5, lane = tid & 31;
    int wm = (wid >> 2) * 64, wn = (wid & 3) * 32;
    int l15 = lane & 15, lh = (lane >> 4) * 8;

    uint32_t abase   = s2u(As) + ((wm + l15) * AST + lh) * 2;
    uint32_t bbase_s = s2u(Bs) + (l15 * BST2 + wn + lh) * 2;

    float c[4][NJ][4];
#pragma unroll
    for (int i = 0; i < 4; i++)
#pragma unroll
        for (int j = 0; j < NJ; j++)
#pragma unroll
            for (int r = 0; r < 4; r++) c[i][j][r] = 0.f;

    int nch = K / 32;
    load_chunk(0, 0); CPA_COMMIT();
    load_chunk(1, 1); CPA_COMMIT();
    load_chunk(2, 2); CPA_COMMIT();

    for (int cc = 0; cc < nch; cc++) {
        int st = cc % NSTG;
        CPA_WAIT2();
        __syncthreads();
        if (cc + 3 < nch) load_chunk(cc + 3, (cc + 3) % NSTG);
        CPA_COMMIT();
#pragma unroll
        for (int kk = 0; kk < 32; kk += 16) {
            uint32_t af[4][4];
#pragma unroll
            for (int mi = 0; mi < 4; mi++)
                LDSM4(af[mi][0], af[mi][1], af[mi][2], af[mi][3],
                      abase + st * ASTG2 + (mi * 16 * AST + kk) * 2);
            uint32_t bq[8];
            LDSM4T(bq[0], bq[1], bq[2], bq[3], bbase_s + st * BSTG2 + (kk * BST2) * 2);
            LDSM4T(bq[4], bq[5], bq[6], bq[7], bbase_s + st * BSTG2 + (kk * BST2 + 16) * 2);
#pragma unroll
            for (int mi = 0; mi < 4; mi++)
#pragma unroll
                for (int nj = 0; nj < NJ; nj++)
                    MMAB(c[mi][nj], af[mi], bq[nj * 2], bq[nj * 2 + 1]);
        }
    }

    __syncthreads();
    int grp = lane >> 2, qid = lane & 3;
#pragma unroll
    for (int mi = 0; mi < 4; mi++) {
#pragma unroll
        for (int half = 0; half < 2; half++) {
            int row = m0 + wm + mi * 16 + grp + half * 8;
            if (row >= M) continue;
            if (MODE == 2) {
                size_t rb2 = (size_t)row * kHID;
#pragma unroll
                for (int njp = 0; njp < NJ; njp += 2) {
                    int cb = n0 + wn + njp * 8 + qid * 2;
                    int oc = ((cb >> 4) << 3) + (cb & 7);
                    float h1a = c[mi][njp][half * 2], h1b = c[mi][njp][half * 2 + 1];
                    float h2a = c[mi][njp + 1][half * 2], h2b = c[mi][njp + 1][half * 2 + 1];
                    float g0 = h1a / (1.f + __expf(-h1a)) * h2a;
                    float g1 = h1b / (1.f + __expf(-h1b)) * h2b;
                    *(__nv_bfloat162*)(Cb + rb2 + oc) = __floats2bfloat162_rn(g0, g1);
                }
                continue;
            }
            size_t rb = (size_t)row * N;
#pragma unroll
            for (int nj = 0; nj < NJ; nj++) {
                int col = n0 + wn + nj * 8 + qid * 2;
                float v0 = c[mi][nj][half * 2 + 0];
                float v1 = c[mi][nj][half * 2 + 1];
                if (MODE == 1) {
                    float g0 = 1.f / (1.f + __expf(-(v0 + bias[col])));
                    float g1 = 1.f / (1.f + __expf(-(v1 + bias[col + 1])));
                    float o0 = X1[rb + col] + X2[rb + col] * g0;
                    float o1 = X1[rb + col + 1] + X2[rb + col + 1] * g1;
                    *(float2*)(C + rb + col) = make_float2(o0, o1);
                } else {
                    *(float2*)(C + rb + col) = make_float2(v0, v1);
                    if (MODE == 0 && Cb)
                        *(__nv_bfloat162*)(Cb + rb + col) = __floats2bfloat162_rn(v0, v1);
                }
            }
        }
    }
}

// ================= bf16 mma flash attention: 128-q x 128-kv tiles (R12-proven) =================
__global__ void __launch_bounds__(256) fattn_k() {
    extern __shared__ char sm_[];
    bf16* Qs = (bf16*)sm_;              // [128][72]
    bf16* Ks = Qs + 128 * 72;           // 2 x [128][72]
    bf16* Vs = Ks + 2 * 128 * 72;       // 2 x [128][72]
    int h = blockIdx.y, q0 = blockIdx.x * 128;
    int tid = threadIdx.x, wid = tid >> 5, lane = tid & 31;
    int l15 = lane & 15, lh = (lane >> 4) * 8;
    int grp = lane >> 2, qid = lane & 3;

    {
        int r = tid >> 1, sb = (tid & 1) * 4;
        const bf16* src = g_qb + (size_t)(q0 + r) * kD + h * 64 + sb * 8;
        uint32_t dst = s2u(Qs + r * 72 + sb * 8);
#pragma unroll
        for (int j = 0; j < 4; j++) CPA16(dst + j * 16, src + j * 8, 16u);
    }
    auto loadKV = [&](int it, int buf) {
        int k0 = it * 128;
        int r = tid >> 1, sb = (tid & 1) * 4;
        const bf16* ks = g_kb + (size_t)(k0 + r) * kD + h * 64 + sb * 8;
        const bf16* vs = g_vb + (size_t)(k0 + r) * kD + h * 64 + sb * 8;
        uint32_t kd = s2u(Ks + buf * 9216 + r * 72 + sb * 8);
        uint32_t vd = s2u(Vs + buf * 9216 + r * 72 + sb * 8);
#pragma unroll
        for (int j = 0; j < 4; j++) { CPA16(kd + j * 16, ks + j * 8, 16u); CPA16(vd + j * 16, vs + j * 8, 16u); }
    };
    loadKV(0, 0); CPA_COMMIT();

    uint32_t qf[4][4];
    float m0 = -1e30f, m1 = -1e30f, l0 = 0.f, l1 = 0.f;
    float co[8][4];
#pragma unroll
    for (int j = 0; j < 8; j++)
#pragma unroll
        for (int r = 0; r < 4; r++) co[j][r] = 0.f;

    for (int it = 0; it < 16; it++) {
        int buf = it & 1;
        if (it + 1 < 16) { loadKV(it + 1, buf ^ 1); CPA_COMMIT(); CPA_WAIT1(); }
        else CPA_WAIT0();
        __syncthreads();
        if (it == 0) {
            uint32_t qb_ = s2u(Qs) + ((wid * 16 + l15) * 72 + lh) * 2;
#pragma unroll
            for (int kk4 = 0; kk4 < 4; kk4++)
                LDSM4(qf[kk4][0], qf[kk4][1], qf[kk4][2], qf[kk4][3], qb_ + kk4 * 32);
        }
        float cs[16][4];
#pragma unroll
        for (int ng = 0; ng < 16; ng++)
#pragma unroll
            for (int r = 0; r < 4; r++) cs[ng][r] = 0.f;
        uint32_t kb_ = s2u(Ks) + buf * 18432;
        int krow = (lane & 7) + ((lane >> 4) << 3);
        int kofs = ((lane >> 3) & 1) << 3;
#pragma unroll
        for (int kk4 = 0; kk4 < 4; kk4++) {
#pragma unroll
            for (int nb = 0; nb < 8; nb++) {
                uint32_t b0, b1, b2, b3;
                LDSM4(b0, b1, b2, b3, kb_ + ((nb * 16 + krow) * 72 + kk4 * 16 + kofs) * 2);
                MMAB(cs[2 * nb], qf[kk4], b0, b1);
                MMAB(cs[2 * nb + 1], qf[kk4], b2, b3);
            }
        }
        float mx0 = -1e30f, mx1 = -1e30f;
#pragma unroll
        for (int ng = 0; ng < 16; ng++) {
            mx0 = fmaxf(mx0, fmaxf(cs[ng][0], cs[ng][1]));
            mx1 = fmaxf(mx1, fmaxf(cs[ng][2], cs[ng][3]));
        }
        mx0 = fmaxf(mx0, __shfl_xor_sync(0xffffffffu, mx0, 1));
        mx0 = fmaxf(mx0, __shfl_xor_sync(0xffffffffu, mx0, 2));
        mx1 = fmaxf(mx1, __shfl_xor_sync(0xffffffffu, mx1, 1));
        mx1 = fmaxf(mx1, __shfl_xor_sync(0xffffffffu, mx1, 2));
        float nm0 = fmaxf(m0, mx0), nm1 = fmaxf(m1, mx1);
        float a0 = __expf(m0 - nm0), a1 = __expf(m1 - nm1);
        l0 *= a0; l1 *= a1;
#pragma unroll
        for (int j = 0; j < 8; j++) {
            co[j][0] *= a0; co[j][1] *= a0; co[j][2] *= a1; co[j][3] *= a1;
        }
#pragma unroll
        for (int ng = 0; ng < 16; ng++) {
            float p0 = __expf(cs[ng][0] - nm0), p1 = __expf(cs[ng][1] - nm0);
            float p2 = __expf(cs[ng][2] - nm1), p3 = __expf(cs[ng][3] - nm1);
            l0 += p0 + p1; l1 += p2 + p3;
            cs[ng][0] = p0; cs[ng][1] = p1; cs[ng][2] = p2; cs[ng][3] = p3;
        }
        m0 = nm0; m1 = nm1;
        uint32_t pf[8][4];
#pragma unroll
        for (int kg = 0; kg < 8; kg++) {
            pf[kg][0] = pack2(cs[2 * kg][0], cs[2 * kg][1]);
            pf[kg][1] = pack2(cs[2 * kg][2], cs[2 * kg][3]);
            pf[kg][2] = pack2(cs[2 * kg + 1][0], cs[2 * kg + 1][1]);
            pf[kg][3] = pack2(cs[2 * kg + 1][2], cs[2 * kg + 1][3]);
        }
        uint32_t vb_ = s2u(Vs) + buf * 18432;
#pragma unroll
        for (int kg = 0; kg < 8; kg++) {
#pragma unroll
            for (int vb = 0; vb < 4; vb++) {
                uint32_t t0, t1, t2, t3;
                LDSM4T(t0, t1, t2, t3, vb_ + ((kg * 16 + l15) * 72 + vb * 16 + lh) * 2);
                MMAB(co[2 * vb], pf[kg], t0, t1);
                MMAB(co[2 * vb + 1], pf[kg], t2, t3);
            }
        }
        __syncthreads();
    }
    l0 += __shfl_xor_sync(0xffffffffu, l0, 1);
    l0 += __shfl_xor_sync(0xffffffffu, l0, 2);
    l1 += __shfl_xor_sync(0xffffffffu, l1, 1);
    l1 += __shfl_xor_sync(0xffffffffu, l1, 2);
    float i0 = 1.f / l0, i1 = 1.f / l1;
    int r0 = q0 + wid * 16 + grp, r1 = r0 + 8;
#pragma unroll
    for (int j = 0; j < 8; j++) {
        int col = h * 64 + j * 8 + qid * 2;
        *(__nv_bfloat162*)(g_attnb + (size_t)r0 * kD + col) = __floats2bfloat162_rn(co[j][0] * i0, co[j][1] * i0);
        *(__nv_bfloat162*)(g_attnb + (size_t)r1 * kD + col) = __floats2bfloat162_rn(co[j][2] * i1, co[j][3] * i1);
    }
}

// ---------------- fp32 -> bf16 convert ----------------
__global__ void cvt_k(const float* __restrict__ s, bf16* __restrict__ d, int n) {
    int stride = gridDim.x * blockDim.x;
    for (int i = blockIdx.x * blockDim.x + threadIdx.x; i * 4 < n; i += stride) {
        float4 v = *(const float4*)(s + i * 4);
        *(__nv_bfloat162*)(d + i * 4)     = __floats2bfloat162_rn(v.x, v.y);
        *(__nv_bfloat162*)(d + i * 4 + 2) = __floats2bfloat162_rn(v.z, v.w);
    }
}

// ---------------- w12 convert + column interleave ----------------
__global__ void cvt_w12i_k(const float* __restrict__ s, bf16* __restrict__ d) {
    int stride = gridDim.x * blockDim.x;
    int total = kE * kD * 1024;
    for (int g = blockIdx.x * blockDim.x + threadIdx.x; g < total; g += stride) {
        int gi = g & 1023;
        int row = g >> 10;
        int src_col = ((gi >> 1) << 3) + ((gi & 1) ? 4096 : 0);
        const float* sp = s + (size_t)row * 8192 + src_col;
        bf16* dp = d + (size_t)row * 8192 + (gi << 3);
        float4 v0 = *(const float4*)sp;
        float4 v1 = *(const float4*)(sp + 4);
        ((__nv_bfloat162*)dp)[0] = __floats2bfloat162_rn(v0.x, v0.y);
        ((__nv_bfloat162*)dp)[1] = __floats2bfloat162_rn(v0.z, v0.w);
        ((__nv_bfloat162*)dp)[2] = __floats2bfloat162_rn(v1.x, v1.y);
        ((__nv_bfloat162*)dp)[3] = __floats2bfloat162_rn(v1.z, v1.w);
    }
}

// ---------------- RMSNorm ----------------
template <bool DUAL>
__global__ void rmsnorm_k(const float* __restrict__ in, bf16* __restrict__ outb,
                          float* __restrict__ outf) {
    int t = threadIdx.x, row = blockIdx.x;
    const float* r = in + (size_t)row * kD;
    float s = 0.f;
#pragma unroll
    for (int i = 0; i < kD / 256; i++) { float v = r[t + i * 256]; s += v * v; }
    __shared__ float red[256];
    red[t] = s; __syncthreads();
    for (int st = 128; st > 0; st >>= 1) { if (t < st) red[t] += red[t + st]; __syncthreads(); }
    float scale = rsqrtf(red[0] / (float)kD + 1e-6f);
#pragma unroll
    for (int i = 0; i < kD / 256; i++) {
        int d = t + i * 256;
        float v = r[d] * scale;
        outb[(size_t)row * kD + d] = __float2bfloat16_rn(v);
        if (DUAL) outf[(size_t)row * kD + d] = v;
    }
}

// ---------------- Householder Q ----------------
__global__ void hh_k(const float* __restrict__ vs) {
    __shared__ float Q[64][64];
    __shared__ float v[64];
    int j = threadIdx.x;
    for (int i = 0; i < 64; i++) Q[i][j] = (i == j) ? 1.f : 0.f;
    __syncthreads();
    for (int r = 0; r < 32; r++) {
        v[j] = vs[r * 64 + j];
        __syncthreads();
        float vn = 1e-8f;
        for (int i = 0; i < 64; i++) vn += v[i] * v[i];
        float w = 0.f;
        for (int i = 0; i < 64; i++) w += v[i] * Q[i][j];
        float sfac = (2.f / vn) * w;
        for (int i = 0; i < 64; i++) Q[i][j] -= sfac * v[i];
        __syncthreads();
    }
    for (int i = 0; i < 64; i++) g_Qm[i * 64 + j] = Q[i][j];
}

// ---------------- cos/sin table ----------------
__global__ void cossin_k(const float* __restrict__ rope_pos, const float* __restrict__ inv_freq) {
    int s = blockIdx.x, f = threadIdx.x;
    float val = 0.f;
    if (f < 15) { int r = f / 5, jj = f % 5; val = rope_pos[s * 3 + r] * inv_freq[jj]; }
    g_cos[s * 32 + f] = cosf(val);
    g_sin[s * 32 + f] = sinf(val);
}

// ---------------- RnRoPE ----------------
__global__ void rope_k() {
    int s = blockIdx.x;
    int t = threadIdx.x;
    int d = t & 63, isk = t >> 6;
    __shared__ float Qm[64][65];
    __shared__ float xin[2][64], t1s[2][64], rots[2][64], cs[32], sn[32];
    for (int i = t; i < 4096; i += 128) Qm[i >> 6][i & 63] = g_Qm[i];
    if (t < 32) { cs[t] = g_cos[s * 32 + t]; sn[t] = g_sin[s * 32 + t]; }
    for (int i = t; i < 1024; i += 128)
        g_vb[(size_t)s * kD + i] = __float2bfloat16_rn(g_qkv[(size_t)s * 3072 + 2048 + i]);
    __syncthreads();
    for (int h = 0; h < kH; h++) {
        xin[isk][d] = g_qkv[(size_t)s * 3072 + isk * 1024 + h * 64 + d];
        __syncthreads();
        float t1 = 0.f;
#pragma unroll
        for (int e = 0; e < 64; e++) t1 += xin[isk][e] * Qm[d][e];
        t1s[isk][d] = t1; __syncthreads();
        float rot;
        if (d < 32) rot = t1 * cs[d]      - t1s[isk][d + 32] * sn[d];
        else        rot = t1 * cs[d - 32] + t1s[isk][d - 32] * sn[d - 32];
        rots[isk][d] = rot; __syncthreads();
        float o = 0.f;
#pragma unroll
        for (int e = 0; e < 64; e++) o += rots[isk][e] * Qm[e][d];
        if (isk) g_kb[(size_t)s * kD + h * 64 + d] = __float2bfloat16_rn(o);
        else     g_qb[(size_t)s * kD + h * 64 + d] = __float2bfloat16_rn(o * 0.125f);
        __syncthreads();
    }
}

// ---------------- router (fp32 — protects top-k) ----------------
__global__ void init_k() { if (threadIdx.x < kE) g_cnt[threadIdx.x] = 0; }

__global__ void router_k(const float* __restrict__ rw_, const float* __restrict__ rb_) {
    int s = blockIdx.x, t = threadIdx.x;
    float loc[8];
#pragma unroll
    for (int e = 0; e < 8; e++) loc[e] = 0.f;
#pragma unroll
    for (int i = 0; i < 4; i++) {
        int d = t + i * 256;
        float xv = g_xn2[(size_t)s * kD + d];
#pragma unroll
        for (int e = 0; e < 8; e++) loc[e] += xv * rw_[d * 8 + e];
    }
    __shared__ float red[8][256];
#pragma unroll
    for (int e = 0; e < 8; e++) red[e][t] = loc[e];
    __syncthreads();
    for (int st = 128; st > 0; st >>= 1) {
        if (t < st)
#pragma unroll
            for (int e = 0; e < 8; e++) red[e][t] += red[e][t + st];
        __syncthreads();
    }
    if (t == 0) {
        float logit[8], sc[8], sq = 0.f;
        for (int e = 0; e < 8; e++) {
            logit[e] = red[e][0] + rb_[e];
            sq += logit[e] * logit[e];
            sc[e] = 1.f / (1.f + __expf(-logit[e]));
        }
        g_rowsum[s] = sq;
        int idx[3]; float val[3]; bool used[8];
        for (int e = 0; e < 8; e++) used[e] = false;
        float tsum = 0.f;
        for (int k = 0; k < 3; k++) {
            int bi = -1; float bv = -1e30f;
            for (int e = 0; e < 8; e++)
                if (!used[e] && sc[e] > bv) { bv = sc[e]; bi = e; }
            used[bi] = true; idx[k] = bi; val[k] = bv; tsum += bv;
        }
        float inv = 1.f / (tsum + 1e-6f);
        for (int k = 0; k < 3; k++) {
            int e = idx[k];
            int pos = atomicAdd(&g_cnt[e], 1);
            g_list[e * kS + pos] = s;
            g_tokslot[s * 3 + k] = e * kS + pos;
            g_tokw[s * 3 + k] = val[k] * inv;
        }
    }
}

// ---------------- combine ----------------
__global__ void combine_k(float* __restrict__ out) {
    int s = blockIdx.x, t = threadIdx.x;
    float w0 = g_tokw[s * 3 + 0], w1 = g_tokw[s * 3 + 1], w2 = g_tokw[s * 3 + 2];
    size_t y0 = (size_t)g_tokslot[s * 3 + 0] * kD;
    size_t y1 = (size_t)g_tokslot[s * 3 + 1] * kD;
    size_t y2 = (size_t)g_tokslot[s * 3 + 2] * kD;
#pragma unroll
    for (int i = 0; i < 4; i++) {
        int d = t + i * 256;
        float v = g_xmid[(size_t)s * kD + d];
        v += w0 * g_ybuf[y0 + d] + w1 * g_ybuf[y1 + d] + w2 * g_ybuf[y2 + d];
        out[(size_t)s * kD + d] = v;
    }
}

// ---------------- aux loss ----------------
__global__ void aux_k(float* __restrict__ out, int out_size) {
    int t = threadIdx.x;
    float sm = 0.f;
    for (int i = t; i < kS; i += 256) sm += g_rowsum[i];
    __shared__ float red[256];
    red[t] = sm; __syncthreads();
    for (int st = 128; st > 0; st >>= 1) { if (t < st) red[t] += red[t + st]; __syncthreads(); }
    if (t == 0 && out_size > kS * kD)
        out[kS * kD] = 0.01f * red[0] / (float)(kS * kE);
}

// ---------------- host ----------------
static const int kSmemG = NSTG * (128 * AST + 32 * BST2) * 2;  // 75776
static const int kSmemA = 92160;

extern "C" void kernel_launch(void* const* d_in, const int* in_sizes, int n_in,
                              void* d_out, int out_size) {
    const float* x        = (const float*)d_in[0];
    const float* rope_pos = (const float*)d_in[1];
    const float* inv_freq = (const float*)d_in[2];
    const float* qkv_w    = (const float*)d_in[3];
    const float* hh_vs    = (const float*)d_in[4];
    const float* out_w    = (const float*)d_in[5];
    const float* gate_w   = (const float*)d_in[6];
    const float* gate_b   = (const float*)d_in[7];
    const float* router_w = (const float*)d_in[8];
    const float* router_b = (const float*)d_in[9];
    const float* w12      = (const float*)d_in[10];
    const float* w3       = (const float*)d_in[11];
    float* outp = (float*)d_out;

    void *p_xnb, *p_qkv, *p_attnb, *p_attnproj, *p_attnprojb, *p_xmid, *p_xn2, *p_xn2b;
    void *p_gbufb, *p_ybuf;
    void *p_wqkvb, *p_woutb, *p_wgateb, *p_w12b, *p_w3b;
    cudaGetSymbolAddress(&p_xnb, g_xnb);
    cudaGetSymbolAddress(&p_qkv, g_qkv);
    cudaGetSymbolAddress(&p_attnb, g_attnb);
    cudaGetSymbolAddress(&p_attnproj, g_attnproj);
    cudaGetSymbolAddress(&p_attnprojb, g_attnprojb);
    cudaGetSymbolAddress(&p_xmid, g_xmid);
    cudaGetSymbolAddress(&p_xn2, g_xn2);
    cudaGetSymbolAddress(&p_xn2b, g_xn2b);
    cudaGetSymbolAddress(&p_gbufb, g_gbufb);
    cudaGetSymbolAddress(&p_ybuf, g_ybuf);
    cudaGetSymbolAddress(&p_wqkvb, g_wqkvb);
    cudaGetSymbolAddress(&p_woutb, g_woutb);
    cudaGetSymbolAddress(&p_wgateb, g_wgateb);
    cudaGetSymbolAddress(&p_w12b, g_w12b);
    cudaGetSymbolAddress(&p_w3b, g_w3b);

    cudaFuncSetAttribute(fattn_k, cudaFuncAttributeMaxDynamicSharedMemorySize, kSmemA);
    cudaFuncSetAttribute(tgemm_k<0>, cudaFuncAttributeMaxDynamicSharedMemorySize, kSmemG);
    cudaFuncSetAttribute(tgemm_k<1>, cudaFuncAttributeMaxDynamicSharedMemorySize, kSmemG);
    cudaFuncSetAttribute(tgemm_k<2>, cudaFuncAttributeMaxDynamicSharedMemorySize, kSmemG);
    cudaFuncSetAttribute(tgemm_k<3>, cudaFuncAttributeMaxDynamicSharedMemorySize, kSmemG);

    // ---- side stream + events (created once; captured work identical every call) ----
    static cudaStream_t s2 = nullptr;
    static cudaEvent_t evFork, evQkv, evOut, evGate, evW12, evW3;
    if (s2 == nullptr) {
        cudaStreamCreateWithFlags(&s2, cudaStreamNonBlocking);
        cudaEventCreateWithFlags(&evFork, cudaEventDisableTiming);
        cudaEventCreateWithFlags(&evQkv,  cudaEventDisableTiming);
        cudaEventCreateWithFlags(&evOut,  cudaEventDisableTiming);
        cudaEventCreateWithFlags(&evGate, cudaEventDisableTiming);
        cudaEventCreateWithFlags(&evW12,  cudaEventDisableTiming);
        cudaEventCreateWithFlags(&evW3,   cudaEventDisableTiming);
    }

    // fork: weight converts on s2, overlapping the attention path
    cudaEventRecord(evFork, 0);
    cudaStreamWaitEvent(s2, evFork, 0);
    cvt_k<<<2048, 256, 0, s2>>>(qkv_w, (bf16*)p_wqkvb, kD * 3 * kD);
    cudaEventRecord(evQkv, s2);
    cvt_k<<<1024, 256, 0, s2>>>(out_w, (bf16*)p_woutb, kD * kD);
    cudaEventRecord(evOut, s2);
    cvt_k<<<1024, 256, 0, s2>>>(gate_w, (bf16*)p_wgateb, kD * kD);
    cudaEventRecord(evGate, s2);
    cvt_w12i_k<<<8192, 256, 0, s2>>>(w12, (bf16*)p_w12b);
    cudaEventRecord(evW12, s2);
    cvt_k<<<8192, 256, 0, s2>>>(w3, (bf16*)p_w3b, kE * kHID * kD);
    cudaEventRecord(evW3, s2);

    // ---- main stream: attention path ----
    rmsnorm_k<false><<<kS, 256>>>(x, (bf16*)p_xnb, nullptr);
    hh_k<<<1, 64>>>(hh_vs);
    cossin_k<<<kS, 32>>>(rope_pos, inv_freq);
    cudaStreamWaitEvent(0, evQkv, 0);
    tgemm_k<0><<<dim3(16, 24, 1), 256, kSmemG>>>((const bf16*)p_xnb,
        (const bf16*)p_wqkvb, (float*)p_qkv, nullptr, kS, 3 * kD, kD,
        nullptr, nullptr, nullptr);
    rope_k<<<kS, 128>>>();
    fattn_k<<<dim3(16, 16, 1), 256, kSmemA>>>();
    cudaStreamWaitEvent(0, evOut, 0);
    tgemm_k<0><<<dim3(16, 8, 1), 256, kSmemG>>>((const bf16*)p_attnb,
        (const bf16*)p_woutb, (float*)p_attnproj, (bf16*)p_attnprojb,
        kS, kD, kD, nullptr, nullptr, nullptr);
    cudaStreamWaitEvent(0, evGate, 0);
    tgemm_k<1><<<dim3(16, 8, 1), 256, kSmemG>>>((const bf16*)p_attnprojb,
        (const bf16*)p_wgateb, (float*)p_xmid, nullptr, kS, kD, kD,
        x, (const float*)p_attnproj, gate_b);

    // ---- MoE path ----
    rmsnorm_k<true><<<kS, 256>>>((const float*)p_xmid, (bf16*)p_xn2b, (float*)p_xn2);
    init_k<<<1, 32>>>();
    router_k<<<kS, 256>>>(router_w, router_b);
    cudaStreamWaitEvent(0, evW12, 0);
    tgemm_k<2><<<dim3(16, 64, 8), 256, kSmemG>>>((const bf16*)p_xn2b,
        (const bf16*)p_w12b, nullptr, (bf16*)p_gbufb, kS, 2 * kHID, kD,
        nullptr, nullptr, nullptr);
    cudaStreamWaitEvent(0, evW3, 0);
    tgemm_k<3><<<dim3(16, 8, 8), 256, kSmemG>>>((const bf16*)p_gbufb,
        (const bf16*)p_w3b, (float*)p_ybuf, nullptr, kS, kD, kHID,
        nullptr, nullptr, nullptr);
    combine_k<<<kS, 256>>>(outp);
    aux_k<<<1, 256>>>(outp, out_size);
}

// round 16
// speedup vs baseline: 1.2562x; 1.0259x over previous
#include <cuda_runtime.h>
#include <cuda_bf16.h>
#include <math.h>
#include <stdint.h>

typedef __nv_bfloat16 bf16;

// ---------------- problem constants ----------------
static const int kS   = 2048;
static const int kD   = 1024;
static const int kH   = 16;
static const int kHD  = 64;
static const int kE   = 8;
static const int kHID = 4096;

// ---------------- scratch ----------------
__device__ bf16  g_xnb     [kS*kD];
__device__ float g_qkv     [kS*3*kD];
__device__ bf16  g_qb      [kS*kD];
__device__ bf16  g_kb      [kS*kD];
__device__ bf16  g_vb      [kS*kD];
__device__ float g_Qm      [kHD*kHD];
__device__ float g_cos     [kS*32];
__device__ float g_sin     [kS*32];
__device__ bf16  g_attnb   [kS*kD];
__device__ float g_attnproj[kS*kD];
__device__ bf16  g_attnprojb[kS*kD];
__device__ float g_xmid    [kS*kD];
__device__ float g_xn2     [kS*kD];
__device__ bf16  g_xn2b    [kS*kD];
__device__ float g_rowsum  [kS];
__device__ int   g_cnt     [kE];
__device__ int   g_list    [kE*kS];
__device__ int   g_tokslot [kS*3];
__device__ float g_tokw    [kS*3];
__device__ bf16  g_gbufb   [kE*kS*kHID];
__device__ float g_ybuf    [kE*kS*kD];
// bf16 weights
__device__ bf16  g_wqkvb   [kD*3*kD];
__device__ bf16  g_woutb   [kD*kD];
__device__ bf16  g_wgateb  [kD*kD];
__device__ bf16  g_w12b    [kE*kD*2*kHID];   // column-interleaved [h1 8 | h2 8 | ...]
__device__ bf16  g_w3b     [kE*kHID*kD];

// ================= helpers =================
static __device__ __forceinline__ uint32_t s2u(const void* p) {
    uint32_t a;
    asm("{ .reg .u64 t; cvta.to.shared.u64 t, %1; cvt.u32.u64 %0, t; }" : "=r"(a) : "l"(p));
    return a;
}
#define CPA16(dst, src, sz) \
    asm volatile("cp.async.cg.shared.global [%0], [%1], 16, %2;" :: "r"(dst), "l"(src), "r"(sz))
#define CPA_COMMIT() asm volatile("cp.async.commit_group;" ::: "memory")
#define CPA_WAIT2()  asm volatile("cp.async.wait_group 2;" ::: "memory")
#define CPA_WAIT1()  asm volatile("cp.async.wait_group 1;" ::: "memory")
#define CPA_WAIT0()  asm volatile("cp.async.wait_group 0;" ::: "memory")

#define LDSM4(r0,r1,r2,r3,addr) \
    asm volatile("ldmatrix.sync.aligned.m8n8.x4.shared.b16 {%0,%1,%2,%3}, [%4];" \
        : "=r"(r0),"=r"(r1),"=r"(r2),"=r"(r3) : "r"(addr))
#define LDSM4T(r0,r1,r2,r3,addr) \
    asm volatile("ldmatrix.sync.aligned.m8n8.x4.trans.shared.b16 {%0,%1,%2,%3}, [%4];" \
        : "=r"(r0),"=r"(r1),"=r"(r2),"=r"(r3) : "r"(addr))

#define MMAB(c, a, b0v, b1v) \
    asm volatile("mma.sync.aligned.m16n8k16.row.col.f32.bf16.bf16.f32 " \
        "{%0,%1,%2,%3}, {%4,%5,%6,%7}, {%8,%9}, {%0,%1,%2,%3};" \
        : "+f"((c)[0]),"+f"((c)[1]),"+f"((c)[2]),"+f"((c)[3]) \
        : "r"((a)[0]),"r"((a)[1]),"r"((a)[2]),"r"((a)[3]), "r"(b0v),"r"(b1v))

static __device__ __forceinline__ uint32_t pack2(float a, float b) {
    __nv_bfloat162 t = __floats2bfloat162_rn(a, b);
    return *(uint32_t*)&t;
}

// ================= bf16 mma GEMM: 4-stage pipeline, block 128x128, K-chunk 32 =================
// 8 warps in 2x4; warp tile 64x32. __launch_bounds__(256,2) => <=128 regs, 2 CTAs/SM.
// MODE 0: C = A@B (+ optional bf16 Cb)
// MODE 1: C = X1 + X2 * sigmoid(A@B + bias)
// MODE 2: MoE pass1, fused SwiGLU: Cb = silu(h1)*h2, w12 col-interleaved
// MODE 3: MoE pass2
#define AST 40
#define BST2 136
#define NSTG 4
template <int MODE>
__global__ void __launch_bounds__(256, 2) tgemm_k(
    const bf16* __restrict__ A, const bf16* __restrict__ B, float* __restrict__ C,
    bf16* __restrict__ Cb, int M, int N, int K,
    const float* __restrict__ X1, const float* __restrict__ X2, const float* __restrict__ bias) {
    const int NJ = 4;
    const uint32_t ASTG2 = 128 * AST * 2;
    const uint32_t BSTG2 = 32 * BST2 * 2;

    extern __shared__ bf16 sm_g[];
    bf16* As = sm_g;                       // NSTG stages [128][AST]
    bf16* Bs = sm_g + NSTG * 128 * AST;    // NSTG stages [32][BST2]

    int tid = threadIdx.x;
    int ez = blockIdx.z;
    const int* rowlist = nullptr;
    if (MODE == 2) {
        M = g_cnt[ez]; rowlist = g_list + ez * kS;
        B += (size_t)ez * (size_t)K * (size_t)N;
        Cb += (size_t)ez * (size_t)kS * (size_t)kHID;
    } else if (MODE == 3) {
        M = g_cnt[ez];
        A += (size_t)ez * (size_t)kS * (size_t)K;
        B += (size_t)ez * (size_t)K * (size_t)N;
        C += (size_t)ez * (size_t)kS * (size_t)N;
    }
    int m0 = blockIdx.x * 128, n0 = blockIdx.y * 128;
    if (m0 >= M) return;

    // ---- A load assignment ----
    int arow = tid >> 2, aseg = tid & 3;
    const bf16* aptr0 = A; const bf16* aptr1 = A;
    uint32_t asz0 = 0, asz1 = 0;
    {
        int r0 = m0 + arow, r1 = r0 + 64;
        if (r0 < M) { int gr = (MODE == 2) ? rowlist[r0] : r0; aptr0 = A + (size_t)gr * K + aseg * 8; asz0 = 16; }
        if (r1 < M) { int gr = (MODE == 2) ? rowlist[r1] : r1; aptr1 = A + (size_t)gr * K + aseg * 8; asz1 = 16; }
    }
    uint32_t adst0 = s2u(As + arow * AST + aseg * 8);
    uint32_t adst1 = s2u(As + (arow + 64) * AST + aseg * 8);

    // ---- B load assignment: 2 segs/thread ----
    int brow = tid >> 4, bseg = tid & 15;
    uint32_t bdst0 = s2u(Bs + brow * BST2 + bseg * 8);
    uint32_t bdst1 = s2u(Bs + (brow + 16) * BST2 + bseg * 8);
    const bf16* bbase = B + n0;

    auto load_chunk = [&](int c, int st) {
        CPA16(adst0 + st * ASTG2, aptr0 + c * 32, asz0);
        CPA16(adst1 + st * ASTG2, aptr1 + c * 32, asz1);
        CPA16(bdst0 + st * BSTG2, bbase + (size_t)(c * 32 + brow) * N + bseg * 8, 16u);
        CPA16(bdst1 + st * BSTG2, bbase + (size_t)(c * 32 + brow + 16) * N + bseg * 8, 16u);
    };

    // ---- warp tiling ----
    int wid = tid >> 5, lane = tid & 31;
    int wm = (wid >> 2) * 64, wn = (wid & 3) * 32;
    int l15 = lane & 15, lh = (lane >> 4) * 8;

    uint32_t abase   = s2u(As) + ((wm + l15) * AST + lh) * 2;
    uint32_t bbase_s = s2u(Bs) + (l15 * BST2 + wn + lh) * 2;

    float c[4][NJ][4];
#pragma unroll
    for (int i = 0; i < 4; i++)
#pragma unroll
        for (int j = 0; j < NJ; j++)
#pragma unroll
            for (int r = 0; r < 4; r++) c[i][j][r] = 0.f;

    int nch = K / 32;
    load_chunk(0, 0); CPA_COMMIT();
    load_chunk(1, 1); CPA_COMMIT();
    load_chunk(2, 2); CPA_COMMIT();

    for (int cc = 0; cc < nch; cc++) {
        int st = cc % NSTG;
        CPA_WAIT2();
        __syncthreads();
        if (cc + 3 < nch) load_chunk(cc + 3, (cc + 3) % NSTG);
        CPA_COMMIT();
#pragma unroll
        for (int kk = 0; kk < 32; kk += 16) {
            uint32_t af[4][4];
#pragma unroll
            for (int mi = 0; mi < 4; mi++)
                LDSM4(af[mi][0], af[mi][1], af[mi][2], af[mi][3],
                      abase + st * ASTG2 + (mi * 16 * AST + kk) * 2);
            uint32_t bq[8];
            LDSM4T(bq[0], bq[1], bq[2], bq[3], bbase_s + st * BSTG2 + (kk * BST2) * 2);
            LDSM4T(bq[4], bq[5], bq[6], bq[7], bbase_s + st * BSTG2 + (kk * BST2 + 16) * 2);
#pragma unroll
            for (int mi = 0; mi < 4; mi++)
#pragma unroll
                for (int nj = 0; nj < NJ; nj++)
                    MMAB(c[mi][nj], af[mi], bq[nj * 2], bq[nj * 2 + 1]);
        }
    }

    __syncthreads();
    int grp = lane >> 2, qid = lane & 3;
#pragma unroll
    for (int mi = 0; mi < 4; mi++) {
#pragma unroll
        for (int half = 0; half < 2; half++) {
            int row = m0 + wm + mi * 16 + grp + half * 8;
            if (row >= M) continue;
            if (MODE == 2) {
                size_t rb2 = (size_t)row * kHID;
#pragma unroll
                for (int njp = 0; njp < NJ; njp += 2) {
                    int cb = n0 + wn + njp * 8 + qid * 2;
                    int oc = ((cb >> 4) << 3) + (cb & 7);
                    float h1a = c[mi][njp][half * 2], h1b = c[mi][njp][half * 2 + 1];
                    float h2a = c[mi][njp + 1][half * 2], h2b = c[mi][njp + 1][half * 2 + 1];
                    float g0 = h1a / (1.f + __expf(-h1a)) * h2a;
                    float g1 = h1b / (1.f + __expf(-h1b)) * h2b;
                    *(__nv_bfloat162*)(Cb + rb2 + oc) = __floats2bfloat162_rn(g0, g1);
                }
                continue;
            }
            size_t rb = (size_t)row * N;
#pragma unroll
            for (int nj = 0; nj < NJ; nj++) {
                int col = n0 + wn + nj * 8 + qid * 2;
                float v0 = c[mi][nj][half * 2 + 0];
                float v1 = c[mi][nj][half * 2 + 1];
                if (MODE == 1) {
                    float g0 = 1.f / (1.f + __expf(-(v0 + bias[col])));
                    float g1 = 1.f / (1.f + __expf(-(v1 + bias[col + 1])));
                    float o0 = X1[rb + col] + X2[rb + col] * g0;
                    float o1 = X1[rb + col + 1] + X2[rb + col + 1] * g1;
                    *(float2*)(C + rb + col) = make_float2(o0, o1);
                } else {
                    *(float2*)(C + rb + col) = make_float2(v0, v1);
                    if (MODE == 0 && Cb)
                        *(__nv_bfloat162*)(Cb + rb + col) = __floats2bfloat162_rn(v0, v1);
                }
            }
        }
    }
}

// ================= bf16 mma flash attention: 128-q x 128-kv tiles (R12-proven) =================
__global__ void __launch_bounds__(256) fattn_k() {
    extern __shared__ char sm_[];
    bf16* Qs = (bf16*)sm_;              // [128][72]
    bf16* Ks = Qs + 128 * 72;           // 2 x [128][72]
    bf16* Vs = Ks + 2 * 128 * 72;       // 2 x [128][72]
    int h = blockIdx.y, q0 = blockIdx.x * 128;
    int tid = threadIdx.x, wid = tid >> 5, lane = tid & 31;
    int l15 = lane & 15, lh = (lane >> 4) * 8;
    int grp = lane >> 2, qid = lane & 3;

    {
        int r = tid >> 1, sb = (tid & 1) * 4;
        const bf16* src = g_qb + (size_t)(q0 + r) * kD + h * 64 + sb * 8;
        uint32_t dst = s2u(Qs + r * 72 + sb * 8);
#pragma unroll
        for (int j = 0; j < 4; j++) CPA16(dst + j * 16, src + j * 8, 16u);
    }
    auto loadKV = [&](int it, int buf) {
        int k0 = it * 128;
        int r = tid >> 1, sb = (tid & 1) * 4;
        const bf16* ks = g_kb + (size_t)(k0 + r) * kD + h * 64 + sb * 8;
        const bf16* vs = g_vb + (size_t)(k0 + r) * kD + h * 64 + sb * 8;
        uint32_t kd = s2u(Ks + buf * 9216 + r * 72 + sb * 8);
        uint32_t vd = s2u(Vs + buf * 9216 + r * 72 + sb * 8);
#pragma unroll
        for (int j = 0; j < 4; j++) { CPA16(kd + j * 16, ks + j * 8, 16u); CPA16(vd + j * 16, vs + j * 8, 16u); }
    };
    loadKV(0, 0); CPA_COMMIT();

    uint32_t qf[4][4];
    float m0 = -1e30f, m1 = -1e30f, l0 = 0.f, l1 = 0.f;
    float co[8][4];
#pragma unroll
    for (int j = 0; j < 8; j++)
#pragma unroll
        for (int r = 0; r < 4; r++) co[j][r] = 0.f;

    for (int it = 0; it < 16; it++) {
        int buf = it & 1;
        if (it + 1 < 16) { loadKV(it + 1, buf ^ 1); CPA_COMMIT(); CPA_WAIT1(); }
        else CPA_WAIT0();
        __syncthreads();
        if (it == 0) {
            uint32_t qb_ = s2u(Qs) + ((wid * 16 + l15) * 72 + lh) * 2;
#pragma unroll
            for (int kk4 = 0; kk4 < 4; kk4++)
                LDSM4(qf[kk4][0], qf[kk4][1], qf[kk4][2], qf[kk4][3], qb_ + kk4 * 32);
        }
        float cs[16][4];
#pragma unroll
        for (int ng = 0; ng < 16; ng++)
#pragma unroll
            for (int r = 0; r < 4; r++) cs[ng][r] = 0.f;
        uint32_t kb_ = s2u(Ks) + buf * 18432;
        int krow = (lane & 7) + ((lane >> 4) << 3);
        int kofs = ((lane >> 3) & 1) << 3;
#pragma unroll
        for (int kk4 = 0; kk4 < 4; kk4++) {
#pragma unroll
            for (int nb = 0; nb < 8; nb++) {
                uint32_t b0, b1, b2, b3;
                LDSM4(b0, b1, b2, b3, kb_ + ((nb * 16 + krow) * 72 + kk4 * 16 + kofs) * 2);
                MMAB(cs[2 * nb], qf[kk4], b0, b1);
                MMAB(cs[2 * nb + 1], qf[kk4], b2, b3);
            }
        }
        float mx0 = -1e30f, mx1 = -1e30f;
#pragma unroll
        for (int ng = 0; ng < 16; ng++) {
            mx0 = fmaxf(mx0, fmaxf(cs[ng][0], cs[ng][1]));
            mx1 = fmaxf(mx1, fmaxf(cs[ng][2], cs[ng][3]));
        }
        mx0 = fmaxf(mx0, __shfl_xor_sync(0xffffffffu, mx0, 1));
        mx0 = fmaxf(mx0, __shfl_xor_sync(0xffffffffu, mx0, 2));
        mx1 = fmaxf(mx1, __shfl_xor_sync(0xffffffffu, mx1, 1));
        mx1 = fmaxf(mx1, __shfl_xor_sync(0xffffffffu, mx1, 2));
        float nm0 = fmaxf(m0, mx0), nm1 = fmaxf(m1, mx1);
        float a0 = __expf(m0 - nm0), a1 = __expf(m1 - nm1);
        l0 *= a0; l1 *= a1;
#pragma unroll
        for (int j = 0; j < 8; j++) {
            co[j][0] *= a0; co[j][1] *= a0; co[j][2] *= a1; co[j][3] *= a1;
        }
#pragma unroll
        for (int ng = 0; ng < 16; ng++) {
            float p0 = __expf(cs[ng][0] - nm0), p1 = __expf(cs[ng][1] - nm0);
            float p2 = __expf(cs[ng][2] - nm1), p3 = __expf(cs[ng][3] - nm1);
            l0 += p0 + p1; l1 += p2 + p3;
            cs[ng][0] = p0; cs[ng][1] = p1; cs[ng][2] = p2; cs[ng][3] = p3;
        }
        m0 = nm0; m1 = nm1;
        uint32_t pf[8][4];
#pragma unroll
        for (int kg = 0; kg < 8; kg++) {
            pf[kg][0] = pack2(cs[2 * kg][0], cs[2 * kg][1]);
            pf[kg][1] = pack2(cs[2 * kg][2], cs[2 * kg][3]);
            pf[kg][2] = pack2(cs[2 * kg + 1][0], cs[2 * kg + 1][1]);
            pf[kg][3] = pack2(cs[2 * kg + 1][2], cs[2 * kg + 1][3]);
        }
        uint32_t vb_ = s2u(Vs) + buf * 18432;
#pragma unroll
        for (int kg = 0; kg < 8; kg++) {
#pragma unroll
            for (int vb = 0; vb < 4; vb++) {
                uint32_t t0, t1, t2, t3;
                LDSM4T(t0, t1, t2, t3, vb_ + ((kg * 16 + l15) * 72 + vb * 16 + lh) * 2);
                MMAB(co[2 * vb], pf[kg], t0, t1);
                MMAB(co[2 * vb + 1], pf[kg], t2, t3);
            }
        }
        __syncthreads();
    }
    l0 += __shfl_xor_sync(0xffffffffu, l0, 1);
    l0 += __shfl_xor_sync(0xffffffffu, l0, 2);
    l1 += __shfl_xor_sync(0xffffffffu, l1, 1);
    l1 += __shfl_xor_sync(0xffffffffu, l1, 2);
    float i0 = 1.f / l0, i1 = 1.f / l1;
    int r0 = q0 + wid * 16 + grp, r1 = r0 + 8;
#pragma unroll
    for (int j = 0; j < 8; j++) {
        int col = h * 64 + j * 8 + qid * 2;
        *(__nv_bfloat162*)(g_attnb + (size_t)r0 * kD + col) = __floats2bfloat162_rn(co[j][0] * i0, co[j][1] * i0);
        *(__nv_bfloat162*)(g_attnb + (size_t)r1 * kD + col) = __floats2bfloat162_rn(co[j][2] * i1, co[j][3] * i1);
    }
}

// ---------------- fp32 -> bf16 convert ----------------
__global__ void cvt_k(const float* __restrict__ s, bf16* __restrict__ d, int n) {
    int stride = gridDim.x * blockDim.x;
    for (int i = blockIdx.x * blockDim.x + threadIdx.x; i * 4 < n; i += stride) {
        float4 v = *(const float4*)(s + i * 4);
        *(__nv_bfloat162*)(d + i * 4)     = __floats2bfloat162_rn(v.x, v.y);
        *(__nv_bfloat162*)(d + i * 4 + 2) = __floats2bfloat162_rn(v.z, v.w);
    }
}

// ---------------- w12 convert + column interleave ----------------
__global__ void cvt_w12i_k(const float* __restrict__ s, bf16* __restrict__ d) {
    int stride = gridDim.x * blockDim.x;
    int total = kE * kD * 1024;
    for (int g = blockIdx.x * blockDim.x + threadIdx.x; g < total; g += stride) {
        int gi = g & 1023;
        int row = g >> 10;
        int src_col = ((gi >> 1) << 3) + ((gi & 1) ? 4096 : 0);
        const float* sp = s + (size_t)row * 8192 + src_col;
        bf16* dp = d + (size_t)row * 8192 + (gi << 3);
        float4 v0 = *(const float4*)sp;
        float4 v1 = *(const float4*)(sp + 4);
        ((__nv_bfloat162*)dp)[0] = __floats2bfloat162_rn(v0.x, v0.y);
        ((__nv_bfloat162*)dp)[1] = __floats2bfloat162_rn(v0.z, v0.w);
        ((__nv_bfloat162*)dp)[2] = __floats2bfloat162_rn(v1.x, v1.y);
        ((__nv_bfloat162*)dp)[3] = __floats2bfloat162_rn(v1.z, v1.w);
    }
}

// ---------------- RMSNorm ----------------
template <bool DUAL>
__global__ void rmsnorm_k(const float* __restrict__ in, bf16* __restrict__ outb,
                          float* __restrict__ outf) {
    int t = threadIdx.x, row = blockIdx.x;
    const float* r = in + (size_t)row * kD;
    float s = 0.f;
#pragma unroll
    for (int i = 0; i < kD / 256; i++) { float v = r[t + i * 256]; s += v * v; }
    __shared__ float red[256];
    red[t] = s; __syncthreads();
    for (int st = 128; st > 0; st >>= 1) { if (t < st) red[t] += red[t + st]; __syncthreads(); }
    float scale = rsqrtf(red[0] / (float)kD + 1e-6f);
#pragma unroll
    for (int i = 0; i < kD / 256; i++) {
        int d = t + i * 256;
        float v = r[d] * scale;
        outb[(size_t)row * kD + d] = __float2bfloat16_rn(v);
        if (DUAL) outf[(size_t)row * kD + d] = v;
    }
}

// ---------------- Householder Q ----------------
__global__ void hh_k(const float* __restrict__ vs) {
    __shared__ float Q[64][64];
    __shared__ float v[64];
    int j = threadIdx.x;
    for (int i = 0; i < 64; i++) Q[i][j] = (i == j) ? 1.f : 0.f;
    __syncthreads();
    for (int r = 0; r < 32; r++) {
        v[j] = vs[r * 64 + j];
        __syncthreads();
        float vn = 1e-8f;
        for (int i = 0; i < 64; i++) vn += v[i] * v[i];
        float w = 0.f;
        for (int i = 0; i < 64; i++) w += v[i] * Q[i][j];
        float sfac = (2.f / vn) * w;
        for (int i = 0; i < 64; i++) Q[i][j] -= sfac * v[i];
        __syncthreads();
    }
    for (int i = 0; i < 64; i++) g_Qm[i * 64 + j] = Q[i][j];
}

// ---------------- cos/sin table ----------------
__global__ void cossin_k(const float* __restrict__ rope_pos, const float* __restrict__ inv_freq) {
    int s = blockIdx.x, f = threadIdx.x;
    float val = 0.f;
    if (f < 15) { int r = f / 5, jj = f % 5; val = rope_pos[s * 3 + r] * inv_freq[jj]; }
    g_cos[s * 32 + f] = cosf(val);
    g_sin[s * 32 + f] = sinf(val);
}

// ---------------- RnRoPE ----------------
__global__ void rope_k() {
    int s = blockIdx.x;
    int t = threadIdx.x;
    int d = t & 63, isk = t >> 6;
    __shared__ float Qm[64][65];
    __shared__ float xin[2][64], t1s[2][64], rots[2][64], cs[32], sn[32];
    for (int i = t; i < 4096; i += 128) Qm[i >> 6][i & 63] = g_Qm[i];
    if (t < 32) { cs[t] = g_cos[s * 32 + t]; sn[t] = g_sin[s * 32 + t]; }
    for (int i = t; i < 1024; i += 128)
        g_vb[(size_t)s * kD + i] = __float2bfloat16_rn(g_qkv[(size_t)s * 3072 + 2048 + i]);
    __syncthreads();
    for (int h = 0; h < kH; h++) {
        xin[isk][d] = g_qkv[(size_t)s * 3072 + isk * 1024 + h * 64 + d];
        __syncthreads();
        float t1 = 0.f;
#pragma unroll
        for (int e = 0; e < 64; e++) t1 += xin[isk][e] * Qm[d][e];
        t1s[isk][d] = t1; __syncthreads();
        float rot;
        if (d < 32) rot = t1 * cs[d]      - t1s[isk][d + 32] * sn[d];
        else        rot = t1 * cs[d - 32] + t1s[isk][d - 32] * sn[d - 32];
        rots[isk][d] = rot; __syncthreads();
        float o = 0.f;
#pragma unroll
        for (int e = 0; e < 64; e++) o += rots[isk][e] * Qm[e][d];
        if (isk) g_kb[(size_t)s * kD + h * 64 + d] = __float2bfloat16_rn(o);
        else     g_qb[(size_t)s * kD + h * 64 + d] = __float2bfloat16_rn(o * 0.125f);
        __syncthreads();
    }
}

// ---------------- router (fp32 — protects top-k) ----------------
__global__ void init_k() { if (threadIdx.x < kE) g_cnt[threadIdx.x] = 0; }

__global__ void router_k(const float* __restrict__ rw_, const float* __restrict__ rb_) {
    int s = blockIdx.x, t = threadIdx.x;
    float loc[8];
#pragma unroll
    for (int e = 0; e < 8; e++) loc[e] = 0.f;
#pragma unroll
    for (int i = 0; i < 4; i++) {
        int d = t + i * 256;
        float xv = g_xn2[(size_t)s * kD + d];
#pragma unroll
        for (int e = 0; e < 8; e++) loc[e] += xv * rw_[d * 8 + e];
    }
    __shared__ float red[8][256];
#pragma unroll
    for (int e = 0; e < 8; e++) red[e][t] = loc[e];
    __syncthreads();
    for (int st = 128; st > 0; st >>= 1) {
        if (t < st)
#pragma unroll
            for (int e = 0; e < 8; e++) red[e][t] += red[e][t + st];
        __syncthreads();
    }
    if (t == 0) {
        float logit[8], sc[8], sq = 0.f;
        for (int e = 0; e < 8; e++) {
            logit[e] = red[e][0] + rb_[e];
            sq += logit[e] * logit[e];
            sc[e] = 1.f / (1.f + __expf(-logit[e]));
        }
        g_rowsum[s] = sq;
        int idx[3]; float val[3]; bool used[8];
        for (int e = 0; e < 8; e++) used[e] = false;
        float tsum = 0.f;
        for (int k = 0; k < 3; k++) {
            int bi = -1; float bv = -1e30f;
            for (int e = 0; e < 8; e++)
                if (!used[e] && sc[e] > bv) { bv = sc[e]; bi = e; }
            used[bi] = true; idx[k] = bi; val[k] = bv; tsum += bv;
        }
        float inv = 1.f / (tsum + 1e-6f);
        for (int k = 0; k < 3; k++) {
            int e = idx[k];
            int pos = atomicAdd(&g_cnt[e], 1);
            g_list[e * kS + pos] = s;
            g_tokslot[s * 3 + k] = e * kS + pos;
            g_tokw[s * 3 + k] = val[k] * inv;
        }
    }
}

// ---------------- combine ----------------
__global__ void combine_k(float* __restrict__ out) {
    int s = blockIdx.x, t = threadIdx.x;
    float w0 = g_tokw[s * 3 + 0], w1 = g_tokw[s * 3 + 1], w2 = g_tokw[s * 3 + 2];
    size_t y0 = (size_t)g_tokslot[s * 3 + 0] * kD;
    size_t y1 = (size_t)g_tokslot[s * 3 + 1] * kD;
    size_t y2 = (size_t)g_tokslot[s * 3 + 2] * kD;
#pragma unroll
    for (int i = 0; i < 4; i++) {
        int d = t + i * 256;
        float v = g_xmid[(size_t)s * kD + d];
        v += w0 * g_ybuf[y0 + d] + w1 * g_ybuf[y1 + d] + w2 * g_ybuf[y2 + d];
        out[(size_t)s * kD + d] = v;
    }
}

// ---------------- aux loss ----------------
__global__ void aux_k(float* __restrict__ out, int out_size) {
    int t = threadIdx.x;
    float sm = 0.f;
    for (int i = t; i < kS; i += 256) sm += g_rowsum[i];
    __shared__ float red[256];
    red[t] = sm; __syncthreads();
    for (int st = 128; st > 0; st >>= 1) { if (t < st) red[t] += red[t + st]; __syncthreads(); }
    if (t == 0 && out_size > kS * kD)
        out[kS * kD] = 0.01f * red[0] / (float)(kS * kE);
}

// ---------------- host ----------------
static const int kSmemG = NSTG * (128 * AST + 32 * BST2) * 2;  // 75776
static const int kSmemA = 92160;

extern "C" void kernel_launch(void* const* d_in, const int* in_sizes, int n_in,
                              void* d_out, int out_size) {
    const float* x        = (const float*)d_in[0];
    const float* rope_pos = (const float*)d_in[1];
    const float* inv_freq = (const float*)d_in[2];
    const float* qkv_w    = (const float*)d_in[3];
    const float* hh_vs    = (const float*)d_in[4];
    const float* out_w    = (const float*)d_in[5];
    const float* gate_w   = (const float*)d_in[6];
    const float* gate_b   = (const float*)d_in[7];
    const float* router_w = (const float*)d_in[8];
    const float* router_b = (const float*)d_in[9];
    const float* w12      = (const float*)d_in[10];
    const float* w3       = (const float*)d_in[11];
    float* outp = (float*)d_out;

    void *p_xnb, *p_qkv, *p_attnb, *p_attnproj, *p_attnprojb, *p_xmid, *p_xn2, *p_xn2b;
    void *p_gbufb, *p_ybuf;
    void *p_wqkvb, *p_woutb, *p_wgateb, *p_w12b, *p_w3b;
    cudaGetSymbolAddress(&p_xnb, g_xnb);
    cudaGetSymbolAddress(&p_qkv, g_qkv);
    cudaGetSymbolAddress(&p_attnb, g_attnb);
    cudaGetSymbolAddress(&p_attnproj, g_attnproj);
    cudaGetSymbolAddress(&p_attnprojb, g_attnprojb);
    cudaGetSymbolAddress(&p_xmid, g_xmid);
    cudaGetSymbolAddress(&p_xn2, g_xn2);
    cudaGetSymbolAddress(&p_xn2b, g_xn2b);
    cudaGetSymbolAddress(&p_gbufb, g_gbufb);
    cudaGetSymbolAddress(&p_ybuf, g_ybuf);
    cudaGetSymbolAddress(&p_wqkvb, g_wqkvb);
    cudaGetSymbolAddress(&p_woutb, g_woutb);
    cudaGetSymbolAddress(&p_wgateb, g_wgateb);
    cudaGetSymbolAddress(&p_w12b, g_w12b);
    cudaGetSymbolAddress(&p_w3b, g_w3b);

    cudaFuncSetAttribute(fattn_k, cudaFuncAttributeMaxDynamicSharedMemorySize, kSmemA);
    cudaFuncSetAttribute(tgemm_k<0>, cudaFuncAttributeMaxDynamicSharedMemorySize, kSmemG);
    cudaFuncSetAttribute(tgemm_k<1>, cudaFuncAttributeMaxDynamicSharedMemorySize, kSmemG);
    cudaFuncSetAttribute(tgemm_k<2>, cudaFuncAttributeMaxDynamicSharedMemorySize, kSmemG);
    cudaFuncSetAttribute(tgemm_k<3>, cudaFuncAttributeMaxDynamicSharedMemorySize, kSmemG);

    // ---- side stream + events (created once; captured work identical every call) ----
    static cudaStream_t s2 = nullptr;
    static cudaEvent_t evFork, evQkv, evHH, evCos, evInit, evOut, evGate, evW12, evW3;
    if (s2 == nullptr) {
        cudaStreamCreateWithFlags(&s2, cudaStreamNonBlocking);
        cudaEventCreateWithFlags(&evFork, cudaEventDisableTiming);
        cudaEventCreateWithFlags(&evQkv,  cudaEventDisableTiming);
        cudaEventCreateWithFlags(&evHH,   cudaEventDisableTiming);
        cudaEventCreateWithFlags(&evCos,  cudaEventDisableTiming);
        cudaEventCreateWithFlags(&evInit, cudaEventDisableTiming);
        cudaEventCreateWithFlags(&evOut,  cudaEventDisableTiming);
        cudaEventCreateWithFlags(&evGate, cudaEventDisableTiming);
        cudaEventCreateWithFlags(&evW12,  cudaEventDisableTiming);
        cudaEventCreateWithFlags(&evW3,   cudaEventDisableTiming);
    }

    // fork: converts + small prep kernels on s2, overlapping the main path
    cudaEventRecord(evFork, 0);
    cudaStreamWaitEvent(s2, evFork, 0);
    cvt_k<<<2048, 256, 0, s2>>>(qkv_w, (bf16*)p_wqkvb, kD * 3 * kD);
    cudaEventRecord(evQkv, s2);
    hh_k<<<1, 64, 0, s2>>>(hh_vs);
    cudaEventRecord(evHH, s2);
    cossin_k<<<kS, 32, 0, s2>>>(rope_pos, inv_freq);
    cudaEventRecord(evCos, s2);
    init_k<<<1, 32, 0, s2>>>();
    cudaEventRecord(evInit, s2);
    cvt_k<<<1024, 256, 0, s2>>>(out_w, (bf16*)p_woutb, kD * kD);
    cudaEventRecord(evOut, s2);
    cvt_k<<<1024, 256, 0, s2>>>(gate_w, (bf16*)p_wgateb, kD * kD);
    cudaEventRecord(evGate, s2);
    cvt_w12i_k<<<8192, 256, 0, s2>>>(w12, (bf16*)p_w12b);
    cudaEventRecord(evW12, s2);
    cvt_k<<<8192, 256, 0, s2>>>(w3, (bf16*)p_w3b, kE * kHID * kD);
    cudaEventRecord(evW3, s2);

    // ---- main stream: attention path ----
    rmsnorm_k<false><<<kS, 256>>>(x, (bf16*)p_xnb, nullptr);
    cudaStreamWaitEvent(0, evQkv, 0);
    tgemm_k<0><<<dim3(16, 24, 1), 256, kSmemG>>>((const bf16*)p_xnb,
        (const bf16*)p_wqkvb, (float*)p_qkv, nullptr, kS, 3 * kD, kD,
        nullptr, nullptr, nullptr);
    cudaStreamWaitEvent(0, evHH, 0);
    cudaStreamWaitEvent(0, evCos, 0);
    rope_k<<<kS, 128>>>();
    fattn_k<<<dim3(16, 16, 1), 256, kSmemA>>>();
    cudaStreamWaitEvent(0, evOut, 0);
    tgemm_k<0><<<dim3(16, 8, 1), 256, kSmemG>>>((const bf16*)p_attnb,
        (const bf16*)p_woutb, (float*)p_attnproj, (bf16*)p_attnprojb,
        kS, kD, kD, nullptr, nullptr, nullptr);
    cudaStreamWaitEvent(0, evGate, 0);
    tgemm_k<1><<<dim3(16, 8, 1), 256, kSmemG>>>((const bf16*)p_attnprojb,
        (const bf16*)p_wgateb, (float*)p_xmid, nullptr, kS, kD, kD,
        x, (const float*)p_attnproj, gate_b);

    // ---- MoE path ----
    rmsnorm_k<true><<<kS, 256>>>((const float*)p_xmid, (bf16*)p_xn2b, (float*)p_xn2);
    cudaStreamWaitEvent(0, evInit, 0);
    router_k<<<kS, 256>>>(router_w, router_b);
    cudaStreamWaitEvent(0, evW12, 0);
    tgemm_k<2><<<dim3(16, 64, 8), 256, kSmemG>>>((const bf16*)p_xn2b,
        (const bf16*)p_w12b, nullptr, (bf16*)p_gbufb, kS, 2 * kHID, kD,
        nullptr, nullptr, nullptr);
    cudaStreamWaitEvent(0, evW3, 0);
    tgemm_k<3><<<dim3(16, 8, 8), 256, kSmemG>>>((const bf16*)p_gbufb,
        (const bf16*)p_w3b, (float*)p_ybuf, nullptr, kS, kD, kHID,
        nullptr, nullptr, nullptr);
    combine_k<<<kS, 256>>>(outp);
    aux_k<<<1, 256>>>(outp, out_size);
}

// round 17
// speedup vs baseline: 1.3108x; 1.0435x over previous
#include <cuda_runtime.h>
#include <cuda_bf16.h>
#include <math.h>
#include <stdint.h>

typedef __nv_bfloat16 bf16;

// ---------------- problem constants ----------------
static const int kS   = 2048;
static const int kD   = 1024;
static const int kH   = 16;
static const int kHD  = 64;
static const int kE   = 8;
static const int kHID = 4096;

// ---------------- scratch ----------------
__device__ bf16  g_xnb     [kS*kD];
__device__ float g_qkv     [kS*3*kD];
__device__ bf16  g_qb      [kS*kD];
__device__ bf16  g_kb      [kS*kD];
__device__ bf16  g_vb      [kS*kD];
__device__ float g_Qm      [kHD*kHD];
__device__ float g_cos     [kS*32];
__device__ float g_sin     [kS*32];
__device__ bf16  g_attnb   [kS*kD];
__device__ float g_attnproj[kS*kD];
__device__ bf16  g_attnprojb[kS*kD];
__device__ float g_xmid    [kS*kD];
__device__ float g_xn2     [kS*kD];
__device__ bf16  g_xn2b    [kS*kD];
__device__ float g_rowsum  [kS];
__device__ int   g_cnt     [kE];
__device__ int   g_list    [kE*kS];
__device__ int   g_tokslot [kS*3];
__device__ float g_tokw    [kS*3];
__device__ bf16  g_gbufb   [kE*kS*kHID];
__device__ float g_ybuf    [kE*kS*kD];
// bf16 weights
__device__ bf16  g_wqkvb   [kD*3*kD];   // q/k blocks pre-rotated by Q^T
__device__ bf16  g_woutb   [kD*kD];
__device__ bf16  g_wgateb  [kD*kD];
__device__ bf16  g_w12b    [kE*kD*2*kHID];   // column-interleaved [h1 8 | h2 8 | ...]
__device__ bf16  g_w3b     [kE*kHID*kD];

// ================= helpers =================
static __device__ __forceinline__ uint32_t s2u(const void* p) {
    uint32_t a;
    asm("{ .reg .u64 t; cvta.to.shared.u64 t, %1; cvt.u32.u64 %0, t; }" : "=r"(a) : "l"(p));
    return a;
}
#define CPA16(dst, src, sz) \
    asm volatile("cp.async.cg.shared.global [%0], [%1], 16, %2;" :: "r"(dst), "l"(src), "r"(sz))
#define CPA_COMMIT() asm volatile("cp.async.commit_group;" ::: "memory")
#define CPA_WAIT2()  asm volatile("cp.async.wait_group 2;" ::: "memory")
#define CPA_WAIT1()  asm volatile("cp.async.wait_group 1;" ::: "memory")
#define CPA_WAIT0()  asm volatile("cp.async.wait_group 0;" ::: "memory")

#define LDSM4(r0,r1,r2,r3,addr) \
    asm volatile("ldmatrix.sync.aligned.m8n8.x4.shared.b16 {%0,%1,%2,%3}, [%4];" \
        : "=r"(r0),"=r"(r1),"=r"(r2),"=r"(r3) : "r"(addr))
#define LDSM4T(r0,r1,r2,r3,addr) \
    asm volatile("ldmatrix.sync.aligned.m8n8.x4.trans.shared.b16 {%0,%1,%2,%3}, [%4];" \
        : "=r"(r0),"=r"(r1),"=r"(r2),"=r"(r3) : "r"(addr))

#define MMAB(c, a, b0v, b1v) \
    asm volatile("mma.sync.aligned.m16n8k16.row.col.f32.bf16.bf16.f32 " \
        "{%0,%1,%2,%3}, {%4,%5,%6,%7}, {%8,%9}, {%0,%1,%2,%3};" \
        : "+f"((c)[0]),"+f"((c)[1]),"+f"((c)[2]),"+f"((c)[3]) \
        : "r"((a)[0]),"r"((a)[1]),"r"((a)[2]),"r"((a)[3]), "r"(b0v),"r"(b1v))

static __device__ __forceinline__ uint32_t pack2(float a, float b) {
    __nv_bfloat162 t = __floats2bfloat162_rn(a, b);
    return *(uint32_t*)&t;
}

// ================= bf16 mma GEMM: 4-stage pipeline, block 128x128, K-chunk 32 =================
#define AST 40
#define BST2 136
#define NSTG 4
template <int MODE>
__global__ void __launch_bounds__(256, 2) tgemm_k(
    const bf16* __restrict__ A, const bf16* __restrict__ B, float* __restrict__ C,
    bf16* __restrict__ Cb, int M, int N, int K,
    const float* __restrict__ X1, const float* __restrict__ X2, const float* __restrict__ bias) {
    const int NJ = 4;
    const uint32_t ASTG2 = 128 * AST * 2;
    const uint32_t BSTG2 = 32 * BST2 * 2;

    extern __shared__ bf16 sm_g[];
    bf16* As = sm_g;
    bf16* Bs = sm_g + NSTG * 128 * AST;

    int tid = threadIdx.x;
    int ez = blockIdx.z;
    const int* rowlist = nullptr;
    if (MODE == 2) {
        M = g_cnt[ez]; rowlist = g_list + ez * kS;
        B += (size_t)ez * (size_t)K * (size_t)N;
        Cb += (size_t)ez * (size_t)kS * (size_t)kHID;
    } else if (MODE == 3) {
        M = g_cnt[ez];
        A += (size_t)ez * (size_t)kS * (size_t)K;
        B += (size_t)ez * (size_t)K * (size_t)N;
        C += (size_t)ez * (size_t)kS * (size_t)N;
    }
    int m0 = blockIdx.x * 128, n0 = blockIdx.y * 128;
    if (m0 >= M) return;

    int arow = tid >> 2, aseg = tid & 3;
    const bf16* aptr0 = A; const bf16* aptr1 = A;
    uint32_t asz0 = 0, asz1 = 0;
    {
        int r0 = m0 + arow, r1 = r0 + 64;
        if (r0 < M) { int gr = (MODE == 2) ? rowlist[r0] : r0; aptr0 = A + (size_t)gr * K + aseg * 8; asz0 = 16; }
        if (r1 < M) { int gr = (MODE == 2) ? rowlist[r1] : r1; aptr1 = A + (size_t)gr * K + aseg * 8; asz1 = 16; }
    }
    uint32_t adst0 = s2u(As + arow * AST + aseg * 8);
    uint32_t adst1 = s2u(As + (arow + 64) * AST + aseg * 8);

    int brow = tid >> 4, bseg = tid & 15;
    uint32_t bdst0 = s2u(Bs + brow * BST2 + bseg * 8);
    uint32_t bdst1 = s2u(Bs + (brow + 16) * BST2 + bseg * 8);
    const bf16* bbase = B + n0;

    auto load_chunk = [&](int c, int st) {
        CPA16(adst0 + st * ASTG2, aptr0 + c * 32, asz0);
        CPA16(adst1 + st * ASTG2, aptr1 + c * 32, asz1);
        CPA16(bdst0 + st * BSTG2, bbase + (size_t)(c * 32 + brow) * N + bseg * 8, 16u);
        CPA16(bdst1 + st * BSTG2, bbase + (size_t)(c * 32 + brow + 16) * N + bseg * 8, 16u);
    };

    int wid = tid >> 5, lane = tid & 31;
    int wm = (wid >> 2) * 64, wn = (wid & 3) * 32;
    int l15 = lane & 15, lh = (lane >> 4) * 8;

    uint32_t abase   = s2u(As) + ((wm + l15) * AST + lh) * 2;
    uint32_t bbase_s = s2u(Bs) + (l15 * BST2 + wn + lh) * 2;

    float c[4][NJ][4];
#pragma unroll
    for (int i = 0; i < 4; i++)
#pragma unroll
        for (int j = 0; j < NJ; j++)
#pragma unroll
            for (int r = 0; r < 4; r++) c[i][j][r] = 0.f;

    int nch = K / 32;
    load_chunk(0, 0); CPA_COMMIT();
    load_chunk(1, 1); CPA_COMMIT();
    load_chunk(2, 2); CPA_COMMIT();

    for (int cc = 0; cc < nch; cc++) {
        int st = cc % NSTG;
        CPA_WAIT2();
        __syncthreads();
        if (cc + 3 < nch) load_chunk(cc + 3, (cc + 3) % NSTG);
        CPA_COMMIT();
#pragma unroll
        for (int kk = 0; kk < 32; kk += 16) {
            uint32_t af[4][4];
#pragma unroll
            for (int mi = 0; mi < 4; mi++)
                LDSM4(af[mi][0], af[mi][1], af[mi][2], af[mi][3],
                      abase + st * ASTG2 + (mi * 16 * AST + kk) * 2);
            uint32_t bq[8];
            LDSM4T(bq[0], bq[1], bq[2], bq[3], bbase_s + st * BSTG2 + (kk * BST2) * 2);
            LDSM4T(bq[4], bq[5], bq[6], bq[7], bbase_s + st * BSTG2 + (kk * BST2 + 16) * 2);
#pragma unroll
            for (int mi = 0; mi < 4; mi++)
#pragma unroll
                for (int nj = 0; nj < NJ; nj++)
                    MMAB(c[mi][nj], af[mi], bq[nj * 2], bq[nj * 2 + 1]);
        }
    }

    __syncthreads();
    int grp = lane >> 2, qid = lane & 3;
#pragma unroll
    for (int mi = 0; mi < 4; mi++) {
#pragma unroll
        for (int half = 0; half < 2; half++) {
            int row = m0 + wm + mi * 16 + grp + half * 8;
            if (row >= M) continue;
            if (MODE == 2) {
                size_t rb2 = (size_t)row * kHID;
#pragma unroll
                for (int njp = 0; njp < NJ; njp += 2) {
                    int cb = n0 + wn + njp * 8 + qid * 2;
                    int oc = ((cb >> 4) << 3) + (cb & 7);
                    float h1a = c[mi][njp][half * 2], h1b = c[mi][njp][half * 2 + 1];
                    float h2a = c[mi][njp + 1][half * 2], h2b = c[mi][njp + 1][half * 2 + 1];
                    float g0 = h1a / (1.f + __expf(-h1a)) * h2a;
                    float g1 = h1b / (1.f + __expf(-h1b)) * h2b;
                    *(__nv_bfloat162*)(Cb + rb2 + oc) = __floats2bfloat162_rn(g0, g1);
                }
                continue;
            }
            size_t rb = (size_t)row * N;
#pragma unroll
            for (int nj = 0; nj < NJ; nj++) {
                int col = n0 + wn + nj * 8 + qid * 2;
                float v0 = c[mi][nj][half * 2 + 0];
                float v1 = c[mi][nj][half * 2 + 1];
                if (MODE == 1) {
                    float g0 = 1.f / (1.f + __expf(-(v0 + bias[col])));
                    float g1 = 1.f / (1.f + __expf(-(v1 + bias[col + 1])));
                    float o0 = X1[rb + col] + X2[rb + col] * g0;
                    float o1 = X1[rb + col + 1] + X2[rb + col + 1] * g1;
                    *(float2*)(C + rb + col) = make_float2(o0, o1);
                } else {
                    *(float2*)(C + rb + col) = make_float2(v0, v1);
                    if (MODE == 0 && Cb)
                        *(__nv_bfloat162*)(Cb + rb + col) = __floats2bfloat162_rn(v0, v1);
                }
            }
        }
    }
}

// ================= bf16 mma flash attention: 128-q x 128-kv tiles =================
__global__ void __launch_bounds__(256) fattn_k() {
    extern __shared__ char sm_[];
    bf16* Qs = (bf16*)sm_;
    bf16* Ks = Qs + 128 * 72;
    bf16* Vs = Ks + 2 * 128 * 72;
    int h = blockIdx.y, q0 = blockIdx.x * 128;
    int tid = threadIdx.x, wid = tid >> 5, lane = tid & 31;
    int l15 = lane & 15, lh = (lane >> 4) * 8;
    int grp = lane >> 2, qid = lane & 3;

    {
        int r = tid >> 1, sb = (tid & 1) * 4;
        const bf16* src = g_qb + (size_t)(q0 + r) * kD + h * 64 + sb * 8;
        uint32_t dst = s2u(Qs + r * 72 + sb * 8);
#pragma unroll
        for (int j = 0; j < 4; j++) CPA16(dst + j * 16, src + j * 8, 16u);
    }
    auto loadKV = [&](int it, int buf) {
        int k0 = it * 128;
        int r = tid >> 1, sb = (tid & 1) * 4;
        const bf16* ks = g_kb + (size_t)(k0 + r) * kD + h * 64 + sb * 8;
        const bf16* vs = g_vb + (size_t)(k0 + r) * kD + h * 64 + sb * 8;
        uint32_t kd = s2u(Ks + buf * 9216 + r * 72 + sb * 8);
        uint32_t vd = s2u(Vs + buf * 9216 + r * 72 + sb * 8);
#pragma unroll
        for (int j = 0; j < 4; j++) { CPA16(kd + j * 16, ks + j * 8, 16u); CPA16(vd + j * 16, vs + j * 8, 16u); }
    };
    loadKV(0, 0); CPA_COMMIT();

    uint32_t qf[4][4];
    float m0 = -1e30f, m1 = -1e30f, l0 = 0.f, l1 = 0.f;
    float co[8][4];
#pragma unroll
    for (int j = 0; j < 8; j++)
#pragma unroll
        for (int r = 0; r < 4; r++) co[j][r] = 0.f;

    for (int it = 0; it < 16; it++) {
        int buf = it & 1;
        if (it + 1 < 16) { loadKV(it + 1, buf ^ 1); CPA_COMMIT(); CPA_WAIT1(); }
        else CPA_WAIT0();
        __syncthreads();
        if (it == 0) {
            uint32_t qb_ = s2u(Qs) + ((wid * 16 + l15) * 72 + lh) * 2;
#pragma unroll
            for (int kk4 = 0; kk4 < 4; kk4++)
                LDSM4(qf[kk4][0], qf[kk4][1], qf[kk4][2], qf[kk4][3], qb_ + kk4 * 32);
        }
        float cs[16][4];
#pragma unroll
        for (int ng = 0; ng < 16; ng++)
#pragma unroll
            for (int r = 0; r < 4; r++) cs[ng][r] = 0.f;
        uint32_t kb_ = s2u(Ks) + buf * 18432;
        int krow = (lane & 7) + ((lane >> 4) << 3);
        int kofs = ((lane >> 3) & 1) << 3;
#pragma unroll
        for (int kk4 = 0; kk4 < 4; kk4++) {
#pragma unroll
            for (int nb = 0; nb < 8; nb++) {
                uint32_t b0, b1, b2, b3;
                LDSM4(b0, b1, b2, b3, kb_ + ((nb * 16 + krow) * 72 + kk4 * 16 + kofs) * 2);
                MMAB(cs[2 * nb], qf[kk4], b0, b1);
                MMAB(cs[2 * nb + 1], qf[kk4], b2, b3);
            }
        }
        float mx0 = -1e30f, mx1 = -1e30f;
#pragma unroll
        for (int ng = 0; ng < 16; ng++) {
            mx0 = fmaxf(mx0, fmaxf(cs[ng][0], cs[ng][1]));
            mx1 = fmaxf(mx1, fmaxf(cs[ng][2], cs[ng][3]));
        }
        mx0 = fmaxf(mx0, __shfl_xor_sync(0xffffffffu, mx0, 1));
        mx0 = fmaxf(mx0, __shfl_xor_sync(0xffffffffu, mx0, 2));
        mx1 = fmaxf(mx1, __shfl_xor_sync(0xffffffffu, mx1, 1));
        mx1 = fmaxf(mx1, __shfl_xor_sync(0xffffffffu, mx1, 2));
        float nm0 = fmaxf(m0, mx0), nm1 = fmaxf(m1, mx1);
        float a0 = __expf(m0 - nm0), a1 = __expf(m1 - nm1);
        l0 *= a0; l1 *= a1;
#pragma unroll
        for (int j = 0; j < 8; j++) {
            co[j][0] *= a0; co[j][1] *= a0; co[j][2] *= a1; co[j][3] *= a1;
        }
#pragma unroll
        for (int ng = 0; ng < 16; ng++) {
            float p0 = __expf(cs[ng][0] - nm0), p1 = __expf(cs[ng][1] - nm0);
            float p2 = __expf(cs[ng][2] - nm1), p3 = __expf(cs[ng][3] - nm1);
            l0 += p0 + p1; l1 += p2 + p3;
            cs[ng][0] = p0; cs[ng][1] = p1; cs[ng][2] = p2; cs[ng][3] = p3;
        }
        m0 = nm0; m1 = nm1;
        uint32_t pf[8][4];
#pragma unroll
        for (int kg = 0; kg < 8; kg++) {
            pf[kg][0] = pack2(cs[2 * kg][0], cs[2 * kg][1]);
            pf[kg][1] = pack2(cs[2 * kg][2], cs[2 * kg][3]);
            pf[kg][2] = pack2(cs[2 * kg + 1][0], cs[2 * kg + 1][1]);
            pf[kg][3] = pack2(cs[2 * kg + 1][2], cs[2 * kg + 1][3]);
        }
        uint32_t vb_ = s2u(Vs) + buf * 18432;
#pragma unroll
        for (int kg = 0; kg < 8; kg++) {
#pragma unroll
            for (int vb = 0; vb < 4; vb++) {
                uint32_t t0, t1, t2, t3;
                LDSM4T(t0, t1, t2, t3, vb_ + ((kg * 16 + l15) * 72 + vb * 16 + lh) * 2);
                MMAB(co[2 * vb], pf[kg], t0, t1);
                MMAB(co[2 * vb + 1], pf[kg], t2, t3);
            }
        }
        __syncthreads();
    }
    l0 += __shfl_xor_sync(0xffffffffu, l0, 1);
    l0 += __shfl_xor_sync(0xffffffffu, l0, 2);
    l1 += __shfl_xor_sync(0xffffffffu, l1, 1);
    l1 += __shfl_xor_sync(0xffffffffu, l1, 2);
    float i0 = 1.f / l0, i1 = 1.f / l1;
    int r0 = q0 + wid * 16 + grp, r1 = r0 + 8;
#pragma unroll
    for (int j = 0; j < 8; j++) {
        int col = h * 64 + j * 8 + qid * 2;
        *(__nv_bfloat162*)(g_attnb + (size_t)r0 * kD + col) = __floats2bfloat162_rn(co[j][0] * i0, co[j][1] * i0);
        *(__nv_bfloat162*)(g_attnb + (size_t)r1 * kD + col) = __floats2bfloat162_rn(co[j][2] * i1, co[j][3] * i1);
    }
}

// ---------------- fp32 -> bf16 convert ----------------
__global__ void cvt_k(const float* __restrict__ s, bf16* __restrict__ d, int n) {
    int stride = gridDim.x * blockDim.x;
    for (int i = blockIdx.x * blockDim.x + threadIdx.x; i * 4 < n; i += stride) {
        float4 v = *(const float4*)(s + i * 4);
        *(__nv_bfloat162*)(d + i * 4)     = __floats2bfloat162_rn(v.x, v.y);
        *(__nv_bfloat162*)(d + i * 4 + 2) = __floats2bfloat162_rn(v.z, v.w);
    }
}

// ---------------- w12 convert + column interleave ----------------
__global__ void cvt_w12i_k(const float* __restrict__ s, bf16* __restrict__ d) {
    int stride = gridDim.x * blockDim.x;
    int total = kE * kD * 1024;
    for (int g = blockIdx.x * blockDim.x + threadIdx.x; g < total; g += stride) {
        int gi = g & 1023;
        int row = g >> 10;
        int src_col = ((gi >> 1) << 3) + ((gi & 1) ? 4096 : 0);
        const float* sp = s + (size_t)row * 8192 + src_col;
        bf16* dp = d + (size_t)row * 8192 + (gi << 3);
        float4 v0 = *(const float4*)sp;
        float4 v1 = *(const float4*)(sp + 4);
        ((__nv_bfloat162*)dp)[0] = __floats2bfloat162_rn(v0.x, v0.y);
        ((__nv_bfloat162*)dp)[1] = __floats2bfloat162_rn(v0.z, v0.w);
        ((__nv_bfloat162*)dp)[2] = __floats2bfloat162_rn(v1.x, v1.y);
        ((__nv_bfloat162*)dp)[3] = __floats2bfloat162_rn(v1.z, v1.w);
    }
}

// ---------------- fold Q^T into q/k weight blocks (bf16 out) ----------------
// Wq'[r, h*64+j] = sum_e W[r, h*64+e] * Q[j, e]   (per-head 64x64, q and k blocks)
__global__ void foldq_k(const float* __restrict__ w) {
    __shared__ float Ws[64][65];
    __shared__ float Qs[64][65];
    int t = threadIdx.x;                 // 256
    int r0 = blockIdx.x * 64;            // 16 row blocks of 64 (kD=1024)
    int hs = blockIdx.y;                 // 32: h + 16*isK
    int h = hs & 15, isk = hs >> 4;
    int cbase = isk * 1024 + h * 64;
    for (int i = t; i < 4096; i += 256) Qs[i >> 6][i & 63] = g_Qm[i];
    for (int i = t; i < 4096; i += 256) {
        int r = i >> 6, e = i & 63;
        Ws[r][e] = w[(size_t)(r0 + r) * 3072 + cbase + e];
    }
    __syncthreads();
    int tr = (t >> 4) * 4, tc = (t & 15) * 4;
    float acc[4][4];
#pragma unroll
    for (int i = 0; i < 4; i++)
#pragma unroll
        for (int j = 0; j < 4; j++) acc[i][j] = 0.f;
#pragma unroll 8
    for (int e = 0; e < 64; e++) {
        float wv[4], qv[4];
#pragma unroll
        for (int i = 0; i < 4; i++) wv[i] = Ws[tr + i][e];
#pragma unroll
        for (int j = 0; j < 4; j++) qv[j] = Qs[tc + j][e];
#pragma unroll
        for (int i = 0; i < 4; i++)
#pragma unroll
            for (int j = 0; j < 4; j++) acc[i][j] += wv[i] * qv[j];
    }
#pragma unroll
    for (int i = 0; i < 4; i++)
#pragma unroll
        for (int j = 0; j < 4; j++)
            g_wqkvb[(size_t)(r0 + tr + i) * 3072 + cbase + tc + j] = __float2bfloat16_rn(acc[i][j]);
}

// ---------------- plain convert of the v-columns of qkv_w ----------------
__global__ void cvtv_k(const float* __restrict__ w) {
    int idx = (blockIdx.x * 256 + threadIdx.x) * 4;   // over kD*1024 v elements
    int row = idx >> 10, col = idx & 1023;
    size_t off = (size_t)row * 3072 + 2048 + col;
    float4 v = *(const float4*)(w + off);
    *(__nv_bfloat162*)(g_wqkvb + off)     = __floats2bfloat162_rn(v.x, v.y);
    *(__nv_bfloat162*)(g_wqkvb + off + 2) = __floats2bfloat162_rn(v.z, v.w);
}

// ---------------- RMSNorm ----------------
template <bool DUAL>
__global__ void rmsnorm_k(const float* __restrict__ in, bf16* __restrict__ outb,
                          float* __restrict__ outf) {
    int t = threadIdx.x, row = blockIdx.x;
    const float* r = in + (size_t)row * kD;
    float s = 0.f;
#pragma unroll
    for (int i = 0; i < kD / 256; i++) { float v = r[t + i * 256]; s += v * v; }
    __shared__ float red[256];
    red[t] = s; __syncthreads();
    for (int st = 128; st > 0; st >>= 1) { if (t < st) red[t] += red[t + st]; __syncthreads(); }
    float scale = rsqrtf(red[0] / (float)kD + 1e-6f);
#pragma unroll
    for (int i = 0; i < kD / 256; i++) {
        int d = t + i * 256;
        float v = r[d] * scale;
        outb[(size_t)row * kD + d] = __float2bfloat16_rn(v);
        if (DUAL) outf[(size_t)row * kD + d] = v;
    }
}

// ---------------- Householder Q ----------------
__global__ void hh_k(const float* __restrict__ vs) {
    __shared__ float Q[64][64];
    __shared__ float v[64];
    int j = threadIdx.x;
    for (int i = 0; i < 64; i++) Q[i][j] = (i == j) ? 1.f : 0.f;
    __syncthreads();
    for (int r = 0; r < 32; r++) {
        v[j] = vs[r * 64 + j];
        __syncthreads();
        float vn = 1e-8f;
        for (int i = 0; i < 64; i++) vn += v[i] * v[i];
        float w = 0.f;
        for (int i = 0; i < 64; i++) w += v[i] * Q[i][j];
        float sfac = (2.f / vn) * w;
        for (int i = 0; i < 64; i++) Q[i][j] -= sfac * v[i];
        __syncthreads();
    }
    for (int i = 0; i < 64; i++) g_Qm[i * 64 + j] = Q[i][j];
}

// ---------------- cos/sin table ----------------
__global__ void cossin_k(const float* __restrict__ rope_pos, const float* __restrict__ inv_freq) {
    int s = blockIdx.x, f = threadIdx.x;
    float val = 0.f;
    if (f < 15) { int r = f / 5, jj = f % 5; val = rope_pos[s * 3 + r] * inv_freq[jj]; }
    g_cos[s * 32 + f] = cosf(val);
    g_sin[s * 32 + f] = sinf(val);
}

// ---------------- elementwise RoPE (Q^T folded into weights; @Q dropped by orthogonality) ----------------
__global__ void ropee_k() {
    int s = blockIdx.x, t = threadIdx.x;   // 256 threads
    __shared__ float cs[32], sn[32];
    if (t < 32) { cs[t] = g_cos[s * 32 + t]; sn[t] = g_sin[s * 32 + t]; }
    __syncthreads();
    const float* src = g_qkv + (size_t)s * 3072;
#pragma unroll
    for (int rep = 0; rep < 4; rep++) {
        int i = t + rep * 256;
        int d = i & 63;
        float v  = src[i],        vp  = src[i ^ 32];
        float v2 = src[1024 + i], vp2 = src[1024 + (i ^ 32)];
        float o, o2;
        if (d < 32) { o = v * cs[d] - vp * sn[d];       o2 = v2 * cs[d] - vp2 * sn[d]; }
        else        { o = v * cs[d - 32] + vp * sn[d - 32]; o2 = v2 * cs[d - 32] + vp2 * sn[d - 32]; }
        g_qb[(size_t)s * kD + i] = __float2bfloat16_rn(o * 0.125f);
        g_kb[(size_t)s * kD + i] = __float2bfloat16_rn(o2);
        g_vb[(size_t)s * kD + i] = __float2bfloat16_rn(src[2048 + i]);
    }
}

// ---------------- router (fp32 — protects top-k) ----------------
__global__ void init_k() { if (threadIdx.x < kE) g_cnt[threadIdx.x] = 0; }

__global__ void router_k(const float* __restrict__ rw_, const float* __restrict__ rb_) {
    int s = blockIdx.x, t = threadIdx.x;
    float loc[8];
#pragma unroll
    for (int e = 0; e < 8; e++) loc[e] = 0.f;
#pragma unroll
    for (int i = 0; i < 4; i++) {
        int d = t + i * 256;
        float xv = g_xn2[(size_t)s * kD + d];
#pragma unroll
        for (int e = 0; e < 8; e++) loc[e] += xv * rw_[d * 8 + e];
    }
    __shared__ float red[8][256];
#pragma unroll
    for (int e = 0; e < 8; e++) red[e][t] = loc[e];
    __syncthreads();
    for (int st = 128; st > 0; st >>= 1) {
        if (t < st)
#pragma unroll
            for (int e = 0; e < 8; e++) red[e][t] += red[e][t + st];
        __syncthreads();
    }
    if (t == 0) {
        float logit[8], sc[8], sq = 0.f;
        for (int e = 0; e < 8; e++) {
            logit[e] = red[e][0] + rb_[e];
            sq += logit[e] * logit[e];
            sc[e] = 1.f / (1.f + __expf(-logit[e]));
        }
        g_rowsum[s] = sq;
        int idx[3]; float val[3]; bool used[8];
        for (int e = 0; e < 8; e++) used[e] = false;
        float tsum = 0.f;
        for (int k = 0; k < 3; k++) {
            int bi = -1; float bv = -1e30f;
            for (int e = 0; e < 8; e++)
                if (!used[e] && sc[e] > bv) { bv = sc[e]; bi = e; }
            used[bi] = true; idx[k] = bi; val[k] = bv; tsum += bv;
        }
        float inv = 1.f / (tsum + 1e-6f);
        for (int k = 0; k < 3; k++) {
            int e = idx[k];
            int pos = atomicAdd(&g_cnt[e], 1);
            g_list[e * kS + pos] = s;
            g_tokslot[s * 3 + k] = e * kS + pos;
            g_tokw[s * 3 + k] = val[k] * inv;
        }
    }
}

// ---------------- combine ----------------
__global__ void combine_k(float* __restrict__ out) {
    int s = blockIdx.x, t = threadIdx.x;
    float w0 = g_tokw[s * 3 + 0], w1 = g_tokw[s * 3 + 1], w2 = g_tokw[s * 3 + 2];
    size_t y0 = (size_t)g_tokslot[s * 3 + 0] * kD;
    size_t y1 = (size_t)g_tokslot[s * 3 + 1] * kD;
    size_t y2 = (size_t)g_tokslot[s * 3 + 2] * kD;
#pragma unroll
    for (int i = 0; i < 4; i++) {
        int d = t + i * 256;
        float v = g_xmid[(size_t)s * kD + d];
        v += w0 * g_ybuf[y0 + d] + w1 * g_ybuf[y1 + d] + w2 * g_ybuf[y2 + d];
        out[(size_t)s * kD + d] = v;
    }
}

// ---------------- aux loss ----------------
__global__ void aux_k(float* __restrict__ out, int out_size) {
    int t = threadIdx.x;
    float sm = 0.f;
    for (int i = t; i < kS; i += 256) sm += g_rowsum[i];
    __shared__ float red[256];
    red[t] = sm; __syncthreads();
    for (int st = 128; st > 0; st >>= 1) { if (t < st) red[t] += red[t + st]; __syncthreads(); }
    if (t == 0 && out_size > kS * kD)
        out[kS * kD] = 0.01f * red[0] / (float)(kS * kE);
}

// ---------------- host ----------------
static const int kSmemG = NSTG * (128 * AST + 32 * BST2) * 2;  // 75776
static const int kSmemA = 92160;

extern "C" void kernel_launch(void* const* d_in, const int* in_sizes, int n_in,
                              void* d_out, int out_size) {
    const float* x        = (const float*)d_in[0];
    const float* rope_pos = (const float*)d_in[1];
    const float* inv_freq = (const float*)d_in[2];
    const float* qkv_w    = (const float*)d_in[3];
    const float* hh_vs    = (const float*)d_in[4];
    const float* out_w    = (const float*)d_in[5];
    const float* gate_w   = (const float*)d_in[6];
    const float* gate_b   = (const float*)d_in[7];
    const float* router_w = (const float*)d_in[8];
    const float* router_b = (const float*)d_in[9];
    const float* w12      = (const float*)d_in[10];
    const float* w3       = (const float*)d_in[11];
    float* outp = (float*)d_out;

    void *p_xnb, *p_qkv, *p_attnb, *p_attnproj, *p_attnprojb, *p_xmid, *p_xn2, *p_xn2b;
    void *p_gbufb, *p_ybuf;
    void *p_wqkvb, *p_woutb, *p_wgateb, *p_w12b, *p_w3b;
    cudaGetSymbolAddress(&p_xnb, g_xnb);
    cudaGetSymbolAddress(&p_qkv, g_qkv);
    cudaGetSymbolAddress(&p_attnb, g_attnb);
    cudaGetSymbolAddress(&p_attnproj, g_attnproj);
    cudaGetSymbolAddress(&p_attnprojb, g_attnprojb);
    cudaGetSymbolAddress(&p_xmid, g_xmid);
    cudaGetSymbolAddress(&p_xn2, g_xn2);
    cudaGetSymbolAddress(&p_xn2b, g_xn2b);
    cudaGetSymbolAddress(&p_gbufb, g_gbufb);
    cudaGetSymbolAddress(&p_ybuf, g_ybuf);
    cudaGetSymbolAddress(&p_wqkvb, g_wqkvb);
    cudaGetSymbolAddress(&p_woutb, g_woutb);
    cudaGetSymbolAddress(&p_wgateb, g_wgateb);
    cudaGetSymbolAddress(&p_w12b, g_w12b);
    cudaGetSymbolAddress(&p_w3b, g_w3b);

    cudaFuncSetAttribute(fattn_k, cudaFuncAttributeMaxDynamicSharedMemorySize, kSmemA);
    cudaFuncSetAttribute(tgemm_k<0>, cudaFuncAttributeMaxDynamicSharedMemorySize, kSmemG);
    cudaFuncSetAttribute(tgemm_k<1>, cudaFuncAttributeMaxDynamicSharedMemorySize, kSmemG);
    cudaFuncSetAttribute(tgemm_k<2>, cudaFuncAttributeMaxDynamicSharedMemorySize, kSmemG);
    cudaFuncSetAttribute(tgemm_k<3>, cudaFuncAttributeMaxDynamicSharedMemorySize, kSmemG);

    // ---- side stream + events (created once; captured work identical every call) ----
    static cudaStream_t s2 = nullptr;
    static cudaEvent_t evFork, evQkv, evCos, evInit, evOut, evGate, evW12, evW3;
    if (s2 == nullptr) {
        cudaStreamCreateWithFlags(&s2, cudaStreamNonBlocking);
        cudaEventCreateWithFlags(&evFork, cudaEventDisableTiming);
        cudaEventCreateWithFlags(&evQkv,  cudaEventDisableTiming);
        cudaEventCreateWithFlags(&evCos,  cudaEventDisableTiming);
        cudaEventCreateWithFlags(&evInit, cudaEventDisableTiming);
        cudaEventCreateWithFlags(&evOut,  cudaEventDisableTiming);
        cudaEventCreateWithFlags(&evGate, cudaEventDisableTiming);
        cudaEventCreateWithFlags(&evW12,  cudaEventDisableTiming);
        cudaEventCreateWithFlags(&evW3,   cudaEventDisableTiming);
    }

    // fork: Q build + weight fold/converts + small prep kernels on s2
    cudaEventRecord(evFork, 0);
    cudaStreamWaitEvent(s2, evFork, 0);
    hh_k<<<1, 64, 0, s2>>>(hh_vs);
    foldq_k<<<dim3(16, 32, 1), 256, 0, s2>>>(qkv_w);
    cvtv_k<<<1024, 256, 0, s2>>>(qkv_w);
    cudaEventRecord(evQkv, s2);
    cossin_k<<<kS, 32, 0, s2>>>(rope_pos, inv_freq);
    cudaEventRecord(evCos, s2);
    init_k<<<1, 32, 0, s2>>>();
    cudaEventRecord(evInit, s2);
    cvt_k<<<1024, 256, 0, s2>>>(out_w, (bf16*)p_woutb, kD * kD);
    cudaEventRecord(evOut, s2);
    cvt_k<<<1024, 256, 0, s2>>>(gate_w, (bf16*)p_wgateb, kD * kD);
    cudaEventRecord(evGate, s2);
    cvt_w12i_k<<<8192, 256, 0, s2>>>(w12, (bf16*)p_w12b);
    cudaEventRecord(evW12, s2);
    cvt_k<<<8192, 256, 0, s2>>>(w3, (bf16*)p_w3b, kE * kHID * kD);
    cudaEventRecord(evW3, s2);

    // ---- main stream: attention path ----
    rmsnorm_k<false><<<kS, 256>>>(x, (bf16*)p_xnb, nullptr);
    cudaStreamWaitEvent(0, evQkv, 0);
    tgemm_k<0><<<dim3(16, 24, 1), 256, kSmemG>>>((const bf16*)p_xnb,
        (const bf16*)p_wqkvb, (float*)p_qkv, nullptr, kS, 3 * kD, kD,
        nullptr, nullptr, nullptr);
    cudaStreamWaitEvent(0, evCos, 0);
    ropee_k<<<kS, 256>>>();
    fattn_k<<<dim3(16, 16, 1), 256, kSmemA>>>();
    cudaStreamWaitEvent(0, evOut, 0);
    tgemm_k<0><<<dim3(16, 8, 1), 256, kSmemG>>>((const bf16*)p_attnb,
        (const bf16*)p_woutb, (float*)p_attnproj, (bf16*)p_attnprojb,
        kS, kD, kD, nullptr, nullptr, nullptr);
    cudaStreamWaitEvent(0, evGate, 0);
    tgemm_k<1><<<dim3(16, 8, 1), 256, kSmemG>>>((const bf16*)p_attnprojb,
        (const bf16*)p_wgateb, (float*)p_xmid, nullptr, kS, kD, kD,
        x, (const float*)p_attnproj, gate_b);

    // ---- MoE path ----
    rmsnorm_k<true><<<kS, 256>>>((const float*)p_xmid, (bf16*)p_xn2b, (float*)p_xn2);
    cudaStreamWaitEvent(0, evInit, 0);
    router_k<<<kS, 256>>>(router_w, router_b);
    cudaStreamWaitEvent(0, evW12, 0);
    tgemm_k<2><<<dim3(16, 64, 8), 256, kSmemG>>>((const bf16*)p_xn2b,
        (const bf16*)p_w12b, nullptr, (bf16*)p_gbufb, kS, 2 * kHID, kD,
        nullptr, nullptr, nullptr);
    cudaStreamWaitEvent(0, evW3, 0);
    tgemm_k<3><<<dim3(16, 8, 8), 256, kSmemG>>>((const bf16*)p_gbufb,
        (const bf16*)p_w3b, (float*)p_ybuf, nullptr, kS, kD, kHID,
        nullptr, nullptr, nullptr);
    combine_k<<<kS, 256>>>(outp);
    aux_k<<<1, 256>>>(outp, out_size);
}